// round 5
// baseline (speedup 1.0000x reference)
#include <cuda_runtime.h>
#include <cstdint>

// ===========================================================================
// PrismDecoder round 5 (= round 4 resubmit after infra failure):
// int16-via-int8 mma.sync GEMMs (exact s32 accumulate, per-(row,kblock)
// scales) + layer-1 M-halving (P = features @ W1, gather-mean in out space).
// Changes vs round 4: removed static guard around cudaFuncSetAttribute.
// ===========================================================================

#define N_VERTS 100000
#define N_FACES 200000
#define MPAD    200064            // 3126 * 64
#define MPAD1   100032            // 1563 * 64
#define DIMD    512

// -------------------- static device scratch (zero-initialized) -------------
__device__ int8_t g_FQH[(size_t)MPAD1 * 512];
__device__ int8_t g_FQL[(size_t)MPAD1 * 512];
__device__ int8_t g_A1H[(size_t)MPAD * 512];
__device__ int8_t g_A1L[(size_t)MPAD * 512];
__device__ int8_t g_A2H[(size_t)MPAD * 512];
__device__ int8_t g_A2L[(size_t)MPAD * 512];
__device__ int8_t g_H3H[(size_t)MPAD * 256];
__device__ int8_t g_H3L[(size_t)MPAD * 256];
__device__ int8_t g_W1H[512 * 512];
__device__ int8_t g_W1L[512 * 512];
__device__ int8_t g_W2H[512 * 512];
__device__ int8_t g_W2L[512 * 512];
__device__ int8_t g_W3H[256 * 512];
__device__ int8_t g_W3L[256 * 512];

__device__ float g_P  [(size_t)MPAD1 * 512];
__device__ float g_SF [(size_t)MPAD1 * 4];
__device__ float g_S1 [(size_t)MPAD * 4];
__device__ float g_S2 [(size_t)MPAD * 4];
__device__ float g_S3 [(size_t)MPAD * 2];
__device__ float g_SW1[512 * 4];
__device__ float g_SW2[512 * 4];
__device__ float g_SW3[256 * 4];

__device__ float g_out12[(size_t)N_FACES * 12];
__device__ float g_summed[(size_t)N_VERTS * 3];
__device__ float g_counts[N_VERTS];

__device__ __forceinline__ int8_t* qsel(int s) {
    switch (s) {
        case 0:  return g_FQH;  case 1:  return g_FQL;
        case 2:  return g_A1H;  case 3:  return g_A1L;
        case 4:  return g_A2H;  case 5:  return g_A2L;
        case 6:  return g_H3H;  case 7:  return g_H3L;
        case 8:  return g_W1H;  case 9:  return g_W1L;
        case 10: return g_W2H;  case 11: return g_W2L;
        case 12: return g_W3H;  default: return g_W3L;
    }
}
__device__ __forceinline__ float* fsel(int s) {
    switch (s) {
        case 0: return g_P;    case 1: return g_SF;
        case 2: return g_S1;   case 3: return g_S2;
        case 4: return g_S3;   case 5: return g_SW1;
        case 6: return g_SW2;  default: return g_SW3;
    }
}

// -------------------- PTX helpers (baseline ISA) ---------------------------
__device__ __forceinline__ uint32_t smem_u32(const void* p) {
    uint32_t a;
    asm("{ .reg .u64 t; cvta.to.shared.u64 t, %1; cvt.u32.u64 %0, t; }"
        : "=r"(a) : "l"(p));
    return a;
}
__device__ __forceinline__ void cp16(uint32_t dst, const void* src) {
    asm volatile("cp.async.cg.shared.global [%0], [%1], 16;"
                 :: "r"(dst), "l"(src));
}
#define CP_COMMIT() asm volatile("cp.async.commit_group;" ::: "memory")
#define CP_WAIT(n)  asm volatile("cp.async.wait_group %0;" :: "n"(n) : "memory")

__device__ __forceinline__ void ldmx4(uint32_t r[4], uint32_t addr) {
    asm volatile("ldmatrix.sync.aligned.m8n8.x4.shared.b16 {%0,%1,%2,%3}, [%4];"
                 : "=r"(r[0]), "=r"(r[1]), "=r"(r[2]), "=r"(r[3]) : "r"(addr));
}
__device__ __forceinline__ void ldmx2(uint32_t r[2], uint32_t addr) {
    asm volatile("ldmatrix.sync.aligned.m8n8.x2.shared.b16 {%0,%1}, [%2];"
                 : "=r"(r[0]), "=r"(r[1]) : "r"(addr));
}

#define MMA_Q8(TA, TB, d, a, b)                                               \
    asm volatile(                                                             \
        "mma.sync.aligned.m16n8k32.row.col.s32." TA "." TB ".s32 "            \
        "{%0,%1,%2,%3}, {%4,%5,%6,%7}, {%8,%9}, {%0,%1,%2,%3};"               \
        : "+r"((d)[0]), "+r"((d)[1]), "+r"((d)[2]), "+r"((d)[3])              \
        : "r"((a)[0]), "r"((a)[1]), "r"((a)[2]), "r"((a)[3]),                 \
          "r"((b)[0]), "r"((b)[1]))

#define SWZC(row, c16) ((uint32_t)((row) * 128 + (((c16) * 16) ^ (((row) & 7) * 16))))

// ---------------------------------------------------------------------------
__global__ void zero_kernel() {
    int i = blockIdx.x * blockDim.x + threadIdx.x;
    if (i < N_VERTS * 3) g_summed[i] = 0.0f;
    if (i < N_VERTS)     g_counts[i] = 0.0f;
}

// ---------------------------------------------------------------------------
// quantize features rows: fp32 [M][512] -> int16 split s8 hi / u8 lo,
// per-(row, 128-k-block) scales. 1 warp per row.
// ---------------------------------------------------------------------------
__global__ __launch_bounds__(256)
void quant_feat_kernel(const float* __restrict__ src, int M) {
    int gw = (blockIdx.x * blockDim.x + threadIdx.x) >> 5;
    int lane = threadIdx.x & 31;
    if (gw >= M) return;
    float v[16];
    #pragma unroll
    for (int t = 0; t < 4; t++) {
        float4 p = *(const float4*)&src[(size_t)gw * 512 + lane * 16 + t * 4];
        v[t*4+0] = p.x; v[t*4+1] = p.y; v[t*4+2] = p.z; v[t*4+3] = p.w;
    }
    float m = 0.0f;
    #pragma unroll
    for (int t = 0; t < 16; t++) m = fmaxf(m, fabsf(v[t]));
    m = fmaxf(m, __shfl_xor_sync(0xffffffffu, m, 1));
    m = fmaxf(m, __shfl_xor_sync(0xffffffffu, m, 2));
    m = fmaxf(m, __shfl_xor_sync(0xffffffffu, m, 4));
    float s   = fmaxf(m, 1e-20f) * (1.0f / 32512.0f);
    float inv = 32512.0f / fmaxf(m, 1e-20f);
    uint32_t wh[4], wl[4];
    #pragma unroll
    for (int j = 0; j < 4; j++) {
        uint32_t ph = 0, pl = 0;
        #pragma unroll
        for (int t = 0; t < 4; t++) {
            int q = __float2int_rn(v[j*4+t] * inv);
            ph |= ((uint32_t)((q >> 8) & 255)) << (t * 8);
            pl |= ((uint32_t)(q & 255)) << (t * 8);
        }
        wh[j] = ph; wl[j] = pl;
    }
    *(uint4*)&g_FQH[(size_t)gw * 512 + lane * 16] = make_uint4(wh[0], wh[1], wh[2], wh[3]);
    *(uint4*)&g_FQL[(size_t)gw * 512 + lane * 16] = make_uint4(wl[0], wl[1], wl[2], wl[3]);
    if ((lane & 7) == 0) g_SF[(size_t)gw * 4 + (lane >> 3)] = s;
}

// ---------------------------------------------------------------------------
// quantize weights: W [K=512][N] fp32 -> Wt [N][512] int16-split, per-(n,kb)
// scales. 1 warp per n.
// ---------------------------------------------------------------------------
__global__ __launch_bounds__(256)
void quant_w_kernel(const float* __restrict__ W, int N,
                    int selH, int selL, int selS) {
    int n = (blockIdx.x * blockDim.x + threadIdx.x) >> 5;
    int lane = threadIdx.x & 31;
    if (n >= N) return;
    float v[16];
    #pragma unroll
    for (int t = 0; t < 16; t++)
        v[t] = W[(size_t)(lane * 16 + t) * N + n];
    float m = 0.0f;
    #pragma unroll
    for (int t = 0; t < 16; t++) m = fmaxf(m, fabsf(v[t]));
    m = fmaxf(m, __shfl_xor_sync(0xffffffffu, m, 1));
    m = fmaxf(m, __shfl_xor_sync(0xffffffffu, m, 2));
    m = fmaxf(m, __shfl_xor_sync(0xffffffffu, m, 4));
    float s   = fmaxf(m, 1e-20f) * (1.0f / 32512.0f);
    float inv = 32512.0f / fmaxf(m, 1e-20f);
    uint32_t wh[4], wl[4];
    #pragma unroll
    for (int j = 0; j < 4; j++) {
        uint32_t ph = 0, pl = 0;
        #pragma unroll
        for (int t = 0; t < 4; t++) {
            int q = __float2int_rn(v[j*4+t] * inv);
            ph |= ((uint32_t)((q >> 8) & 255)) << (t * 8);
            pl |= ((uint32_t)(q & 255)) << (t * 8);
        }
        wh[j] = ph; wl[j] = pl;
    }
    *(uint4*)&qsel(selH)[(size_t)n * 512 + lane * 16] = make_uint4(wh[0], wh[1], wh[2], wh[3]);
    *(uint4*)&qsel(selL)[(size_t)n * 512 + lane * 16] = make_uint4(wl[0], wl[1], wl[2], wl[3]);
    if ((lane & 7) == 0) fsel(selS)[(size_t)n * 4 + (lane >> 3)] = s;
}

// ---------------------------------------------------------------------------
// int16-split int8 GEMM: C = A[M,512] @ Wt[N,512]^T, CTA tile 64x128,
// 8 warps of 64x16, BK=128 bytes, 3-stage cp.async, k32 s8/u8 MMAs.
// mode 0: store fp32 into P. mode 1: bias+relu+requantize to s8 hi/lo + scale.
// ---------------------------------------------------------------------------
#define QSTAGE 49152   // Ah 8K | Al 8K | Bh 16K | Bl 16K
#define QSMEM  (3 * QSTAGE)

__global__ __launch_bounds__(256, 1)
void gemm_q8_kernel(int selAH, int selAL, int selSA,
                    int selWH, int selWL, int selSW,
                    const float* __restrict__ bias, int mode,
                    int selOH, int selOL, int selSO, int No)
{
    extern __shared__ char smem[];
    __shared__ int s_amax[64];
    const uint32_t sb = smem_u32(smem);
    const int tid  = threadIdx.x;
    const int lane = tid & 31;
    const int warp = tid >> 5;
    const int warpN = warp * 16;
    const size_t mBase = (size_t)blockIdx.y * 64;
    const size_t nBase = (size_t)blockIdx.x * 128;

    const int8_t* __restrict__ AH = qsel(selAH);
    const int8_t* __restrict__ AL = qsel(selAL);
    const int8_t* __restrict__ WH = qsel(selWH);
    const int8_t* __restrict__ WL = qsel(selWL);
    const float*  __restrict__ SA = fsel(selSA);
    const float*  __restrict__ SW = fsel(selSW);

    const int aRow   = (lane & 7) + ((lane >> 3) & 1) * 8;
    const int aColH  = lane >> 4;
    const int bRow   = lane & 7;
    const int bColH  = (lane >> 3) & 1;
    const int rowq   = lane >> 2;        // C frag row
    const int colq   = (lane & 3) * 2;   // C frag col pair

    float facc[4][2][4];
    #pragma unroll
    for (int i = 0; i < 4; i++)
        #pragma unroll
        for (int j = 0; j < 2; j++)
            #pragma unroll
            for (int q = 0; q < 4; q++) facc[i][j][q] = 0.0f;

    auto load_stage = [&](int c, int s) {
        uint32_t base = sb + s * QSTAGE;
        #pragma unroll
        for (int it = 0; it < 2; it++) {
            int ch = tid + it * 256;           // 0..511
            int r = ch >> 3, c16 = ch & 7;
            uint32_t sw = SWZC(r, c16);
            size_t g = (mBase + r) * 512 + (size_t)c * 128 + c16 * 16;
            cp16(base + sw,        AH + g);
            cp16(base + 8192 + sw, AL + g);
        }
        #pragma unroll
        for (int it = 0; it < 4; it++) {
            int ch = tid + it * 256;           // 0..1023
            int r = ch >> 3, c16 = ch & 7;
            uint32_t sw = SWZC(r, c16);
            size_t g = (nBase + r) * 512 + (size_t)c * 128 + c16 * 16;
            cp16(base + 16384 + sw, WH + g);
            cp16(base + 32768 + sw, WL + g);
        }
        CP_COMMIT();
    };

    load_stage(0, 0);
    load_stage(1, 1);

    #pragma unroll 1
    for (int c = 0; c < 4; c++) {
        if (c < 3) { CP_WAIT(1); } else { CP_WAIT(0); }
        __syncthreads();
        if (c + 2 < 4) load_stage(c + 2, (c + 2) % 3);

        const uint32_t stA  = sb + (c % 3) * QSTAGE;
        const uint32_t stAl = stA + 8192;
        const uint32_t stB  = stA + 16384;
        const uint32_t stBl = stA + 32768;

        int hh[4][2][4], cr[4][2][4], ll[4][2][4];
        #pragma unroll
        for (int i = 0; i < 4; i++)
            #pragma unroll
            for (int j = 0; j < 2; j++)
                #pragma unroll
                for (int q = 0; q < 4; q++) { hh[i][j][q] = 0; cr[i][j][q] = 0; ll[i][j][q] = 0; }

        #pragma unroll
        for (int ks = 0; ks < 4; ks++) {
            uint32_t ah[4][4], al[4][4];
            const int cA = ks * 2 + aColH;
            #pragma unroll
            for (int i = 0; i < 4; i++) {
                uint32_t off = SWZC(i * 16 + aRow, cA);
                ldmx4(ah[i], stA + off);
                ldmx4(al[i], stAl + off);
            }
            uint32_t bh[2][2], bl[2][2];
            const int cB = ks * 2 + bColH;
            #pragma unroll
            for (int j = 0; j < 2; j++) {
                uint32_t off = SWZC(warpN + j * 8 + bRow, cB);
                ldmx2(bh[j], stB + off);
                ldmx2(bl[j], stBl + off);
            }
            #pragma unroll
            for (int i = 0; i < 4; i++)
                #pragma unroll
                for (int j = 0; j < 2; j++) {
                    MMA_Q8("s8", "s8", hh[i][j], ah[i], bh[j]);
                    MMA_Q8("s8", "u8", cr[i][j], ah[i], bl[j]);
                    MMA_Q8("u8", "s8", cr[i][j], al[i], bh[j]);
                    MMA_Q8("u8", "u8", ll[i][j], al[i], bl[j]);
                }
        }

        // dequant chunk into fp32 accumulators
        float sa[4][2], sbc[2][2];
        #pragma unroll
        for (int i = 0; i < 4; i++) {
            sa[i][0] = __ldg(&SA[(mBase + i * 16 + rowq) * 4 + c]);
            sa[i][1] = __ldg(&SA[(mBase + i * 16 + rowq + 8) * 4 + c]);
        }
        #pragma unroll
        for (int j = 0; j < 2; j++) {
            sbc[j][0] = __ldg(&SW[(nBase + warpN + j * 8 + colq) * 4 + c]);
            sbc[j][1] = __ldg(&SW[(nBase + warpN + j * 8 + colq + 1) * 4 + c]);
        }
        #pragma unroll
        for (int i = 0; i < 4; i++)
            #pragma unroll
            for (int j = 0; j < 2; j++)
                #pragma unroll
                for (int q = 0; q < 4; q++) {
                    float ss = sa[i][q >> 1] * sbc[j][q & 1];
                    float t = fmaf((float)hh[i][j][q], 65536.0f,
                              fmaf((float)cr[i][j][q], 256.0f,
                                   (float)ll[i][j][q]));
                    facc[i][j][q] = fmaf(t, ss, facc[i][j][q]);
                }
    }

    if (mode == 0) {
        // store fp32 (P), no bias/relu
        float* __restrict__ P = fsel(0);
        #pragma unroll
        for (int i = 0; i < 4; i++)
            #pragma unroll
            for (int j = 0; j < 2; j++) {
                size_t col = nBase + warpN + j * 8 + colq;
                size_t r0 = mBase + i * 16 + rowq;
                *(float2*)&P[r0 * 512 + col]       = make_float2(facc[i][j][0], facc[i][j][1]);
                *(float2*)&P[(r0 + 8) * 512 + col] = make_float2(facc[i][j][2], facc[i][j][3]);
            }
        return;
    }

    // mode 1: bias + relu + per-(row, this-128-block) quantize
    float v[4][2][4];
    #pragma unroll
    for (int i = 0; i < 4; i++)
        #pragma unroll
        for (int j = 0; j < 2; j++) {
            size_t col = nBase + warpN + j * 8 + colq;
            float b0 = __ldg(&bias[col]);
            float b1 = __ldg(&bias[col + 1]);
            v[i][j][0] = fmaxf(facc[i][j][0] + b0, 0.0f);
            v[i][j][1] = fmaxf(facc[i][j][1] + b1, 0.0f);
            v[i][j][2] = fmaxf(facc[i][j][2] + b0, 0.0f);
            v[i][j][3] = fmaxf(facc[i][j][3] + b1, 0.0f);
        }
    __syncthreads();
    if (tid < 64) s_amax[tid] = 0;
    __syncthreads();
    #pragma unroll
    for (int i = 0; i < 4; i++) {
        float m0 = 0.0f, m1 = 0.0f;
        #pragma unroll
        for (int j = 0; j < 2; j++) {
            m0 = fmaxf(m0, fmaxf(v[i][j][0], v[i][j][1]));
            m1 = fmaxf(m1, fmaxf(v[i][j][2], v[i][j][3]));
        }
        atomicMax(&s_amax[i * 16 + rowq],     __float_as_int(m0));
        atomicMax(&s_amax[i * 16 + rowq + 8], __float_as_int(m1));
    }
    __syncthreads();

    int8_t* __restrict__ OH = qsel(selOH);
    int8_t* __restrict__ OL = qsel(selOL);
    #pragma unroll
    for (int i = 0; i < 4; i++) {
        float a0 = fmaxf(__int_as_float(s_amax[i * 16 + rowq]),     1e-20f);
        float a1 = fmaxf(__int_as_float(s_amax[i * 16 + rowq + 8]), 1e-20f);
        float inv0 = 32512.0f / a0;
        float inv1 = 32512.0f / a1;
        #pragma unroll
        for (int j = 0; j < 2; j++) {
            size_t col = nBase + warpN + j * 8 + colq;
            size_t r0 = mBase + i * 16 + rowq;
            int q0 = __float2int_rn(v[i][j][0] * inv0);
            int q1 = __float2int_rn(v[i][j][1] * inv0);
            int q2 = __float2int_rn(v[i][j][2] * inv1);
            int q3 = __float2int_rn(v[i][j][3] * inv1);
            uint16_t h01 = (uint16_t)(((q0 >> 8) & 255) | (((q1 >> 8) & 255) << 8));
            uint16_t l01 = (uint16_t)((q0 & 255) | ((q1 & 255) << 8));
            uint16_t h23 = (uint16_t)(((q2 >> 8) & 255) | (((q3 >> 8) & 255) << 8));
            uint16_t l23 = (uint16_t)((q2 & 255) | ((q3 & 255) << 8));
            *(uint16_t*)&OH[r0 * No + col]       = h01;
            *(uint16_t*)&OL[r0 * No + col]       = l01;
            *(uint16_t*)&OH[(r0 + 8) * No + col] = h23;
            *(uint16_t*)&OL[(r0 + 8) * No + col] = l23;
        }
    }
    if (tid < 64) {
        float a = fmaxf(__int_as_float(s_amax[tid]), 1e-20f);
        fsel(selSO)[(mBase + tid) * (No >> 7) + blockIdx.x] = a * (1.0f / 32512.0f);
    }
}

// ---------------------------------------------------------------------------
// h1 = relu(mean3(P[faces]) + b1), quantized. 1 warp per face.
// ---------------------------------------------------------------------------
__global__ __launch_bounds__(256)
void gather_mean_quant_kernel(const int* __restrict__ faces,
                              const float* __restrict__ b1) {
    int f = (blockIdx.x * blockDim.x + threadIdx.x) >> 5;
    int lane = threadIdx.x & 31;
    if (f >= N_FACES) return;
    int i0 = __ldg(&faces[f * 3 + 0]);
    int i1 = __ldg(&faces[f * 3 + 1]);
    int i2 = __ldg(&faces[f * 3 + 2]);
    const float* __restrict__ P = g_P;
    float v[16];
    #pragma unroll
    for (int t = 0; t < 4; t++) {
        int col = lane * 16 + t * 4;
        float4 p0 = *(const float4*)&P[(size_t)i0 * 512 + col];
        float4 p1 = *(const float4*)&P[(size_t)i1 * 512 + col];
        float4 p2 = *(const float4*)&P[(size_t)i2 * 512 + col];
        const float k = 1.0f / 3.0f;
        v[t*4+0] = fmaxf((p0.x + p1.x + p2.x) * k + __ldg(&b1[col + 0]), 0.0f);
        v[t*4+1] = fmaxf((p0.y + p1.y + p2.y) * k + __ldg(&b1[col + 1]), 0.0f);
        v[t*4+2] = fmaxf((p0.z + p1.z + p2.z) * k + __ldg(&b1[col + 2]), 0.0f);
        v[t*4+3] = fmaxf((p0.w + p1.w + p2.w) * k + __ldg(&b1[col + 3]), 0.0f);
    }
    float m = 0.0f;
    #pragma unroll
    for (int t = 0; t < 16; t++) m = fmaxf(m, v[t]);
    m = fmaxf(m, __shfl_xor_sync(0xffffffffu, m, 1));
    m = fmaxf(m, __shfl_xor_sync(0xffffffffu, m, 2));
    m = fmaxf(m, __shfl_xor_sync(0xffffffffu, m, 4));
    float s   = fmaxf(m, 1e-20f) * (1.0f / 32512.0f);
    float inv = 32512.0f / fmaxf(m, 1e-20f);
    uint32_t wh[4], wl[4];
    #pragma unroll
    for (int j = 0; j < 4; j++) {
        uint32_t ph = 0, pl = 0;
        #pragma unroll
        for (int t = 0; t < 4; t++) {
            int q = __float2int_rn(v[j*4+t] * inv);
            ph |= ((uint32_t)((q >> 8) & 255)) << (t * 8);
            pl |= ((uint32_t)(q & 255)) << (t * 8);
        }
        wh[j] = ph; wl[j] = pl;
    }
    *(uint4*)&g_A1H[(size_t)f * 512 + lane * 16] = make_uint4(wh[0], wh[1], wh[2], wh[3]);
    *(uint4*)&g_A1L[(size_t)f * 512 + lane * 16] = make_uint4(wl[0], wl[1], wl[2], wl[3]);
    if ((lane & 7) == 0) g_S1[(size_t)f * 4 + (lane >> 3)] = s;
}

// ---------------------------------------------------------------------------
// out12 = h3 @ W4 + b4 (dequant h3 on the fly)
// ---------------------------------------------------------------------------
__global__ __launch_bounds__(128)
void out12_kernel(const float* __restrict__ W4, const float* __restrict__ b4) {
    __shared__ float ws[256 * 12];
    for (int i = threadIdx.x; i < 256 * 12; i += blockDim.x) ws[i] = W4[i];
    __syncthreads();
    int r = blockIdx.x * blockDim.x + threadIdx.x;
    if (r >= N_FACES) return;
    const int8_t* xh = g_H3H + (size_t)r * 256;
    const int8_t* xl = g_H3L + (size_t)r * 256;
    float s0 = g_S3[(size_t)r * 2 + 0];
    float s1 = g_S3[(size_t)r * 2 + 1];
    float acc[12];
    #pragma unroll
    for (int n = 0; n < 12; n++) acc[n] = b4[n];
    #pragma unroll 4
    for (int k0 = 0; k0 < 256; k0 += 4) {
        uint32_t uh = *(const uint32_t*)&xh[k0];
        uint32_t ul = *(const uint32_t*)&xl[k0];
        float s = (k0 < 128) ? s0 : s1;
        #pragma unroll
        for (int t = 0; t < 4; t++) {
            int h = (int)(char)((uh >> (t * 8)) & 255);
            int l = (int)((ul >> (t * 8)) & 255);
            float val = s * (float)((h << 8) | l);
            const float* wr = &ws[(k0 + t) * 12];
            #pragma unroll
            for (int n = 0; n < 12; n++)
                acc[n] = fmaf(val, wr[n], acc[n]);
        }
    }
    #pragma unroll
    for (int n = 0; n < 12; n++) g_out12[(size_t)r * 12 + n] = acc[n];
}

// ---------------------------------------------------------------------------
// 3x3 Jacobi + special procrustes + transform + segment atomics
// ---------------------------------------------------------------------------
__device__ __forceinline__ void jrot(float A[3][3], float V[3][3],
                                     int p, int q, int r) {
    float apq = A[p][q];
    if (fabsf(apq) < 1e-20f) return;
    float tau = (A[q][q] - A[p][p]) / (2.0f * apq);
    float t = copysignf(1.0f, tau) / (fabsf(tau) + sqrtf(1.0f + tau * tau));
    float c = rsqrtf(1.0f + t * t);
    float s = t * c;
    A[p][p] -= t * apq;
    A[q][q] += t * apq;
    A[p][q] = 0.0f; A[q][p] = 0.0f;
    float arp = A[r][p], arq = A[r][q];
    A[r][p] = c * arp - s * arq; A[p][r] = A[r][p];
    A[r][q] = s * arp + c * arq; A[q][r] = A[r][q];
    #pragma unroll
    for (int k = 0; k < 3; k++) {
        float vkp = V[k][p], vkq = V[k][q];
        V[k][p] = c * vkp - s * vkq;
        V[k][q] = s * vkp + c * vkq;
    }
}

__device__ __forceinline__ void cross3(const float a[3], const float b[3], float o[3]) {
    o[0] = a[1] * b[2] - a[2] * b[1];
    o[1] = a[2] * b[0] - a[0] * b[2];
    o[2] = a[0] * b[1] - a[1] * b[0];
}

__global__ __launch_bounds__(256)
void procrustes_kernel(const float* __restrict__ verts,
                       const int*   __restrict__ faces,
                       float* __restrict__ out) {
    int f = blockIdx.x * blockDim.x + threadIdx.x;
    if (f >= N_FACES) return;

    float o[12];
    #pragma unroll
    for (int i = 0; i < 12; i++) o[i] = g_out12[(size_t)f * 12 + i];

    float m[3][3];
    #pragma unroll
    for (int i = 0; i < 3; i++)
        #pragma unroll
        for (int j = 0; j < 3; j++) m[i][j] = o[3 * i + j];

    float fr = 0.0f;
    #pragma unroll
    for (int i = 0; i < 3; i++)
        #pragma unroll
        for (int j = 0; j < 3; j++) fr += m[i][j] * m[i][j];
    float inv = rsqrtf(fmaxf(fr, 1e-30f));
    #pragma unroll
    for (int i = 0; i < 3; i++)
        #pragma unroll
        for (int j = 0; j < 3; j++) m[i][j] *= inv;

    float A[3][3];
    #pragma unroll
    for (int i = 0; i < 3; i++)
        #pragma unroll
        for (int j = 0; j < 3; j++) {
            float s = 0.0f;
            #pragma unroll
            for (int k = 0; k < 3; k++) s += m[k][i] * m[k][j];
            A[i][j] = s;
        }
    float V[3][3] = {{1,0,0},{0,1,0},{0,0,1}};

    #pragma unroll
    for (int sweep = 0; sweep < 6; sweep++) {
        jrot(A, V, 0, 1, 2);
        jrot(A, V, 0, 2, 1);
        jrot(A, V, 1, 2, 0);
    }

    float w0 = A[0][0], w1 = A[1][1], w2 = A[2][2];
    int imax = (w0 >= w1) ? (w0 >= w2 ? 0 : 2) : (w1 >= w2 ? 1 : 2);
    int imin = (w0 <= w1) ? (w0 <= w2 ? 0 : 2) : (w1 <= w2 ? 1 : 2);
    if (imax == imin) imin = (imax + 1) % 3;
    int imid = 3 - imax - imin;

    float v1[3] = {V[0][imax], V[1][imax], V[2][imax]};
    float v2[3] = {V[0][imid], V[1][imid], V[2][imid]};

    float u1[3], u2[3];
    #pragma unroll
    for (int a = 0; a < 3; a++)
        u1[a] = m[a][0] * v1[0] + m[a][1] * v1[1] + m[a][2] * v1[2];
    float n1 = sqrtf(u1[0]*u1[0] + u1[1]*u1[1] + u1[2]*u1[2]);
    if (n1 > 1e-12f) {
        float in1 = 1.0f / n1;
        u1[0] *= in1; u1[1] *= in1; u1[2] *= in1;
    } else { u1[0] = 1.0f; u1[1] = 0.0f; u1[2] = 0.0f; }

    #pragma unroll
    for (int a = 0; a < 3; a++)
        u2[a] = m[a][0] * v2[0] + m[a][1] * v2[1] + m[a][2] * v2[2];
    float d = u2[0]*u1[0] + u2[1]*u1[1] + u2[2]*u1[2];
    u2[0] -= d * u1[0]; u2[1] -= d * u1[1]; u2[2] -= d * u1[2];
    float n2 = sqrtf(u2[0]*u2[0] + u2[1]*u2[1] + u2[2]*u2[2]);
    if (n2 > 1e-10f) {
        float in2 = 1.0f / n2;
        u2[0] *= in2; u2[1] *= in2; u2[2] *= in2;
    } else {
        float e[3] = {0.f, 0.f, 0.f};
        e[(fabsf(u1[0]) < 0.9f) ? 0 : 1] = 1.0f;
        cross3(u1, e, u2);
        float nn = rsqrtf(fmaxf(u2[0]*u2[0]+u2[1]*u2[1]+u2[2]*u2[2], 1e-30f));
        u2[0] *= nn; u2[1] *= nn; u2[2] *= nn;
    }

    float u3[3], v3[3];
    cross3(u1, u2, u3);
    cross3(v1, v2, v3);

    float R[3][3];
    #pragma unroll
    for (int a = 0; a < 3; a++)
        #pragma unroll
        for (int b = 0; b < 3; b++)
            R[a][b] = u1[a]*v1[b] + u2[a]*v2[b] + u3[a]*v3[b];

    float* rot_out = out + (size_t)(N_VERTS * 3) + (size_t)N_FACES * 9 + (size_t)f * 9;
    #pragma unroll
    for (int a = 0; a < 3; a++)
        #pragma unroll
        for (int b = 0; b < 3; b++)
            rot_out[a * 3 + b] = R[a][b];

    float t0 = o[9], t1 = o[10], t2 = o[11];
    float* tp_out = out + (size_t)(N_VERTS * 3) + (size_t)f * 9;
    #pragma unroll
    for (int j = 0; j < 3; j++) {
        int vi = faces[f * 3 + j];
        float p0 = verts[(size_t)vi * 3 + 0];
        float p1 = verts[(size_t)vi * 3 + 1];
        float p2 = verts[(size_t)vi * 3 + 2];
        float tpx = p0 * R[0][0] + p1 * R[1][0] + p2 * R[2][0] + t0;
        float tpy = p0 * R[0][1] + p1 * R[1][1] + p2 * R[2][1] + t1;
        float tpz = p0 * R[0][2] + p1 * R[1][2] + p2 * R[2][2] + t2;
        tp_out[j * 3 + 0] = tpx;
        tp_out[j * 3 + 1] = tpy;
        tp_out[j * 3 + 2] = tpz;
        atomicAdd(&g_summed[(size_t)vi * 3 + 0], tpx);
        atomicAdd(&g_summed[(size_t)vi * 3 + 1], tpy);
        atomicAdd(&g_summed[(size_t)vi * 3 + 2], tpz);
        atomicAdd(&g_counts[vi], 1.0f);
    }
}

__global__ void finalize_kernel(float* __restrict__ out) {
    int v = blockIdx.x * blockDim.x + threadIdx.x;
    if (v >= N_VERTS) return;
    float c = fmaxf(g_counts[v], 1.0f);
    float ic = 1.0f / c;
    out[(size_t)v * 3 + 0] = g_summed[(size_t)v * 3 + 0] * ic;
    out[(size_t)v * 3 + 1] = g_summed[(size_t)v * 3 + 1] * ic;
    out[(size_t)v * 3 + 2] = g_summed[(size_t)v * 3 + 2] * ic;
}

// ---------------------------------------------------------------------------
extern "C" void kernel_launch(void* const* d_in, const int* in_sizes, int n_in,
                              void* d_out, int out_size) {
    const float* verts    = (const float*)d_in[0];
    const float* features = (const float*)d_in[1];
    const int*   faces    = (const int*)  d_in[2];
    const float* W1 = (const float*)d_in[3];
    const float* b1 = (const float*)d_in[4];
    const float* W2 = (const float*)d_in[5];
    const float* b2 = (const float*)d_in[6];
    const float* W3 = (const float*)d_in[7];
    const float* b3 = (const float*)d_in[8];
    const float* W4 = (const float*)d_in[9];
    const float* b4 = (const float*)d_in[10];
    float* out = (float*)d_out;

    (void)in_sizes; (void)n_in; (void)out_size;

    // Not a stream op; safe under graph capture, idempotent, no static guard.
    cudaFuncSetAttribute(gemm_q8_kernel,
                         cudaFuncAttributeMaxDynamicSharedMemorySize,
                         QSMEM);

    zero_kernel<<<(N_VERTS * 3 + 255) / 256, 256>>>();

    // quantize inputs
    quant_feat_kernel<<<(N_VERTS * 32 + 255) / 256, 256>>>(features, N_VERTS);
    quant_w_kernel<<<(512 * 32 + 255) / 256, 256>>>(W1, 512, 8, 9, 5);
    quant_w_kernel<<<(512 * 32 + 255) / 256, 256>>>(W2, 512, 10, 11, 6);
    quant_w_kernel<<<(256 * 32 + 255) / 256, 256>>>(W3, 256, 12, 13, 7);

    // P = features @ W1t^T  (M = 100032, fp32 out)
    gemm_q8_kernel<<<dim3(4, MPAD1 / 64), 256, QSMEM>>>(
        0, 1, 1, 8, 9, 5, b1, 0, 0, 0, 0, 512);

    // h1 = relu(mean3(P[faces]) + b1) quantized
    gather_mean_quant_kernel<<<(N_FACES * 32 + 255) / 256, 256>>>(faces, b1);

    // h2 = relu(h1 @ W2t^T + b2) quantized
    gemm_q8_kernel<<<dim3(4, MPAD / 64), 256, QSMEM>>>(
        2, 3, 2, 10, 11, 6, b2, 1, 4, 5, 3, 512);

    // h3 = relu(h2 @ W3t^T + b3) quantized
    gemm_q8_kernel<<<dim3(2, MPAD / 64), 256, QSMEM>>>(
        4, 5, 3, 12, 13, 7, b3, 1, 6, 7, 4, 256);

    out12_kernel<<<(N_FACES + 127) / 128, 128>>>(W4, b4);

    procrustes_kernel<<<(N_FACES + 255) / 256, 256>>>(verts, faces, out);

    finalize_kernel<<<(N_VERTS + 255) / 256, 256>>>(out);
}

// round 7
// speedup vs baseline: 3.0406x; 3.0406x over previous
#include <cuda_runtime.h>
#include <cuda_bf16.h>
#include <cstdint>

// ===========================================================================
// PrismDecoder round 7 (= round 6 resubmit after infra failure):
// validated split-bf16 mma.sync GEMM + (a) layer-1 M-halving via
// P = features @ W1, (b) 512-thread / 16-warp GEMM CTAs.
// ===========================================================================

#define N_VERTS 100000
#define N_FACES 200000
#define MPAD    200064            // 1563 * 128
#define MPAD1   100096            // 782  * 128
#define DIMD    512

// -------------------- static device scratch (zero-initialized) -------------
__device__ __nv_bfloat16 g_FH[(size_t)MPAD1 * 512];   // features hi
__device__ __nv_bfloat16 g_FL[(size_t)MPAD1 * 512];   // features lo
__device__ float         g_P [(size_t)MPAD1 * 512];   // features @ W1
__device__ __nv_bfloat16 g_A1H[(size_t)MPAD * 512];   // h1 hi
__device__ __nv_bfloat16 g_A1L[(size_t)MPAD * 512];
__device__ __nv_bfloat16 g_A2H[(size_t)MPAD * 512];   // h2 hi
__device__ __nv_bfloat16 g_A2L[(size_t)MPAD * 512];
__device__ __nv_bfloat16 g_H3H[(size_t)MPAD * 256];
__device__ __nv_bfloat16 g_H3L[(size_t)MPAD * 256];
// transposed weights [N][K] bf16 hi/lo
__device__ __nv_bfloat16 g_W1H[512 * 512];
__device__ __nv_bfloat16 g_W1L[512 * 512];
__device__ __nv_bfloat16 g_W2H[512 * 512];
__device__ __nv_bfloat16 g_W2L[512 * 512];
__device__ __nv_bfloat16 g_W3H[256 * 512];
__device__ __nv_bfloat16 g_W3L[256 * 512];
__device__ float g_out12[(size_t)N_FACES * 12];
__device__ float g_summed[(size_t)N_VERTS * 3];
__device__ float g_counts[N_VERTS];

__device__ __forceinline__ __nv_bfloat16* bsel(int s) {
    switch (s) {
        case 0:  return g_FH;   case 1:  return g_FL;
        case 2:  return g_A1H;  case 3:  return g_A1L;
        case 4:  return g_A2H;  case 5:  return g_A2L;
        case 6:  return g_H3H;  case 7:  return g_H3L;
        case 8:  return g_W1H;  case 9:  return g_W1L;
        case 10: return g_W2H;  case 11: return g_W2L;
        case 12: return g_W3H;  default: return g_W3L;
    }
}

// -------------------- PTX helpers (baseline ISA) ---------------------------
__device__ __forceinline__ uint32_t smem_u32(const void* p) {
    uint32_t a;
    asm("{ .reg .u64 t; cvta.to.shared.u64 t, %1; cvt.u32.u64 %0, t; }"
        : "=r"(a) : "l"(p));
    return a;
}
__device__ __forceinline__ void cp16(uint32_t dst, const void* src) {
    asm volatile("cp.async.cg.shared.global [%0], [%1], 16;"
                 :: "r"(dst), "l"(src));
}
#define CP_COMMIT() asm volatile("cp.async.commit_group;" ::: "memory")
#define CP_WAIT(n)  asm volatile("cp.async.wait_group %0;" :: "n"(n) : "memory")

__device__ __forceinline__ void ldmx4(uint32_t r[4], uint32_t addr) {
    asm volatile("ldmatrix.sync.aligned.m8n8.x4.shared.b16 {%0,%1,%2,%3}, [%4];"
                 : "=r"(r[0]), "=r"(r[1]), "=r"(r[2]), "=r"(r[3]) : "r"(addr));
}
__device__ __forceinline__ void ldmx2(uint32_t r[2], uint32_t addr) {
    asm volatile("ldmatrix.sync.aligned.m8n8.x2.shared.b16 {%0,%1}, [%2];"
                 : "=r"(r[0]), "=r"(r[1]) : "r"(addr));
}
__device__ __forceinline__ void mma16816(float d[4], const uint32_t a[4],
                                         const uint32_t b[2]) {
    asm volatile(
        "mma.sync.aligned.m16n8k16.row.col.f32.bf16.bf16.f32 "
        "{%0,%1,%2,%3}, {%4,%5,%6,%7}, {%8,%9}, {%0,%1,%2,%3};"
        : "+f"(d[0]), "+f"(d[1]), "+f"(d[2]), "+f"(d[3])
        : "r"(a[0]), "r"(a[1]), "r"(a[2]), "r"(a[3]), "r"(b[0]), "r"(b[1]));
}
__device__ __forceinline__ uint32_t packbf2(__nv_bfloat16 a, __nv_bfloat16 b) {
    return (uint32_t)__bfloat16_as_ushort(a) |
           ((uint32_t)__bfloat16_as_ushort(b) << 16);
}
#define SWZC(row, c16) ((uint32_t)((row) * 128 + (((c16) * 16) ^ (((row) & 7) * 16))))

// ---------------------------------------------------------------------------
__global__ void zero_kernel() {
    int i = blockIdx.x * blockDim.x + threadIdx.x;
    if (i < N_VERTS * 3) g_summed[i] = 0.0f;
    if (i < N_VERTS)     g_counts[i] = 0.0f;
}

// weight transpose + hi/lo split:  W [K][N] fp32 -> Wt [N][K] bf16 hi/lo
__global__ void convert_w(const float* __restrict__ W, int selH, int selL, int N) {
    int idx = blockIdx.x * blockDim.x + threadIdx.x;     // n*512 + k
    if (idx >= N * 512) return;
    int n = idx >> 9, k = idx & 511;
    float v = W[(size_t)k * N + n];
    __nv_bfloat16 h = __float2bfloat16(v);
    bsel(selH)[idx] = h;
    bsel(selL)[idx] = __float2bfloat16(v - __bfloat162float(h));
}

// features fp32 -> bf16 hi/lo (elementwise, no gather)
__global__ void split_feat_kernel(const float* __restrict__ features) {
    int idx = blockIdx.x * blockDim.x + threadIdx.x;      // float4 chunks
    if (idx >= N_VERTS * 128) return;
    size_t o = (size_t)idx * 4;
    float4 p = *(const float4*)&features[o];
    __nv_bfloat16 h0 = __float2bfloat16(p.x);
    __nv_bfloat16 h1 = __float2bfloat16(p.y);
    __nv_bfloat16 h2 = __float2bfloat16(p.z);
    __nv_bfloat16 h3 = __float2bfloat16(p.w);
    __nv_bfloat16 l0 = __float2bfloat16(p.x - __bfloat162float(h0));
    __nv_bfloat16 l1 = __float2bfloat16(p.y - __bfloat162float(h1));
    __nv_bfloat16 l2 = __float2bfloat16(p.z - __bfloat162float(h2));
    __nv_bfloat16 l3 = __float2bfloat16(p.w - __bfloat162float(h3));
    *(uint2*)&g_FH[o] = make_uint2(packbf2(h0, h1), packbf2(h2, h3));
    *(uint2*)&g_FL[o] = make_uint2(packbf2(l0, l1), packbf2(l2, l3));
}

// ---------------------------------------------------------------------------
// Split-bf16 HMMA GEMM: out = [relu](in[M,512] @ Wt[N,512]^T [+ bias])
// BM=128 BN=128 BK=64, 512 threads (16 warps 4x4, warp tile 32x32),
// 2-stage cp.async pipeline (128KB), SW128 swizzled 128B K-major rows.
// 3 MMA products per tile: Ah*Bh + Ah*Bl + Al*Bh.
// mode 0: fp32 out to g_P (no bias/relu).  mode 1: bias+relu+split bf16.
// ---------------------------------------------------------------------------
#define GSTAGE 65536              // Ah 16K | Al 16K | Bh 16K | Bl 16K
#define GSMEM  (2 * GSTAGE)

__global__ __launch_bounds__(512, 1)
void gemm_mma_kernel(int selInH, int selInL, int selWH, int selWL,
                     const float* __restrict__ bias, int mode,
                     int selOutH, int selOutL, int Ncols)
{
    extern __shared__ char smem[];
    const uint32_t sb = smem_u32(smem);
    const int tid  = threadIdx.x;
    const int lane = tid & 31;
    const int warp = tid >> 5;              // 0..15
    const int warpM = (warp >> 2) * 32;     // 0,32,64,96
    const int warpN = (warp & 3) * 32;      // 0,32,64,96
    const size_t mBase = (size_t)blockIdx.y * 128;
    const size_t nBase = (size_t)blockIdx.x * 128;

    const __nv_bfloat16* __restrict__ inH = bsel(selInH);
    const __nv_bfloat16* __restrict__ inL = bsel(selInL);
    const __nv_bfloat16* __restrict__ wH  = bsel(selWH);
    const __nv_bfloat16* __restrict__ wL  = bsel(selWL);

    // ldmatrix per-lane geometry (validated round 3)
    const int aRow   = (lane & 7) + ((lane >> 3) & 1) * 8;   // row within 16
    const int aColSl = lane >> 4;                            // 0/1 (16B col)
    const int bRow   = lane & 7;
    const int bColSl = (lane >> 3) & 1;

    float acc[2][4][4];
    #pragma unroll
    for (int i = 0; i < 2; i++)
        #pragma unroll
        for (int j = 0; j < 4; j++)
            #pragma unroll
            for (int q = 0; q < 4; q++) acc[i][j][q] = 0.0f;

    auto load_stage = [&](int c, int s) {
        uint32_t base = sb + s * GSTAGE;
        #pragma unroll
        for (int i = 0; i < 2; i++) {
            int ch = tid + i * 512;          // 0..1023
            int r = ch >> 3, c16 = ch & 7;
            uint32_t sw = SWZC(r, c16);
            size_t ga = (mBase + r) * 512 + (size_t)c * 64 + c16 * 8;
            size_t gb = (nBase + r) * 512 + (size_t)c * 64 + c16 * 8;
            cp16(base + sw,         inH + ga);
            cp16(base + 16384 + sw, inL + ga);
            cp16(base + 32768 + sw, wH + gb);
            cp16(base + 49152 + sw, wL + gb);
        }
        CP_COMMIT();
    };

    load_stage(0, 0);
    load_stage(1, 1);

    #pragma unroll 1
    for (int c = 0; c < 8; c++) {
        if (c < 7) { CP_WAIT(1); } else { CP_WAIT(0); }
        __syncthreads();

        const uint32_t aBh = sb + (c & 1) * GSTAGE;
        const uint32_t aBl = aBh + 16384;
        const uint32_t bBh = aBh + 32768;
        const uint32_t bBl = aBh + 49152;

        #pragma unroll
        for (int ks = 0; ks < 4; ks++) {
            uint32_t ah[2][4], al[2][4];
            const int cA = ks * 2 + aColSl;
            #pragma unroll
            for (int i = 0; i < 2; i++) {
                int row = warpM + i * 16 + aRow;
                uint32_t off = SWZC(row, cA);
                ldmx4(ah[i], aBh + off);
                ldmx4(al[i], aBl + off);
            }
            uint32_t bh[4][2], bl[4][2];
            const int cB = ks * 2 + bColSl;
            #pragma unroll
            for (int j = 0; j < 4; j++) {
                int row = warpN + j * 8 + bRow;
                uint32_t off = SWZC(row, cB);
                ldmx2(bh[j], bBh + off);
                ldmx2(bl[j], bBl + off);
            }
            #pragma unroll
            for (int i = 0; i < 2; i++)
                #pragma unroll
                for (int j = 0; j < 4; j++) {
                    mma16816(acc[i][j], ah[i], bh[j]);
                    mma16816(acc[i][j], ah[i], bl[j]);
                    mma16816(acc[i][j], al[i], bh[j]);
                }
        }

        if (c + 2 < 8) {
            __syncthreads();           // all reads of stage (c&1) complete
            load_stage(c + 2, c & 1);
        }
    }

    // ---- epilogue ----
    const int colq = (lane & 3) * 2;
    const int rowq = lane >> 2;

    if (mode == 0) {
        float* __restrict__ P = g_P;
        #pragma unroll
        for (int j = 0; j < 4; j++) {
            size_t col = nBase + warpN + j * 8 + colq;
            #pragma unroll
            for (int i = 0; i < 2; i++) {
                size_t row0 = mBase + warpM + i * 16 + rowq;
                *(float2*)&P[row0 * 512 + col] =
                    make_float2(acc[i][j][0], acc[i][j][1]);
                *(float2*)&P[(row0 + 8) * 512 + col] =
                    make_float2(acc[i][j][2], acc[i][j][3]);
            }
        }
        return;
    }

    __nv_bfloat16* __restrict__ oH = bsel(selOutH);
    __nv_bfloat16* __restrict__ oL = bsel(selOutL);
    #pragma unroll
    for (int j = 0; j < 4; j++) {
        size_t col = nBase + warpN + j * 8 + colq;
        float b0 = __ldg(&bias[col]);
        float b1 = __ldg(&bias[col + 1]);
        #pragma unroll
        for (int i = 0; i < 2; i++) {
            size_t row0 = mBase + warpM + i * 16 + rowq;
            size_t row1 = row0 + 8;
            float v00 = fmaxf(acc[i][j][0] + b0, 0.0f);
            float v01 = fmaxf(acc[i][j][1] + b1, 0.0f);
            float v10 = fmaxf(acc[i][j][2] + b0, 0.0f);
            float v11 = fmaxf(acc[i][j][3] + b1, 0.0f);
            __nv_bfloat16 h00 = __float2bfloat16(v00);
            __nv_bfloat16 h01 = __float2bfloat16(v01);
            __nv_bfloat16 h10 = __float2bfloat16(v10);
            __nv_bfloat16 h11 = __float2bfloat16(v11);
            __nv_bfloat16 l00 = __float2bfloat16(v00 - __bfloat162float(h00));
            __nv_bfloat16 l01 = __float2bfloat16(v01 - __bfloat162float(h01));
            __nv_bfloat16 l10 = __float2bfloat16(v10 - __bfloat162float(h10));
            __nv_bfloat16 l11 = __float2bfloat16(v11 - __bfloat162float(h11));
            *(uint32_t*)&oH[row0 * Ncols + col] = packbf2(h00, h01);
            *(uint32_t*)&oH[row1 * Ncols + col] = packbf2(h10, h11);
            *(uint32_t*)&oL[row0 * Ncols + col] = packbf2(l00, l01);
            *(uint32_t*)&oL[row1 * Ncols + col] = packbf2(l10, l11);
        }
    }
}

// ---------------------------------------------------------------------------
// h1 = relu(mean3(P[faces]) + b1) -> bf16 hi/lo.
// one thread per (face, float4-chunk); 128 chunks per face.
// ---------------------------------------------------------------------------
__global__ void gather_mean_split_kernel(const int* __restrict__ faces,
                                         const float* __restrict__ b1) {
    int idx = blockIdx.x * blockDim.x + threadIdx.x;
    int f  = idx >> 7;
    int c4 = (idx & 127) << 2;
    if (f >= N_FACES) return;
    int i0 = __ldg(&faces[f * 3 + 0]);
    int i1 = __ldg(&faces[f * 3 + 1]);
    int i2 = __ldg(&faces[f * 3 + 2]);
    float4 a = *(const float4*)&g_P[(size_t)i0 * DIMD + c4];
    float4 b = *(const float4*)&g_P[(size_t)i1 * DIMD + c4];
    float4 c = *(const float4*)&g_P[(size_t)i2 * DIMD + c4];
    float4 bb = *(const float4*)&b1[c4];
    const float k = 1.0f / 3.0f;
    float v0 = fmaxf((a.x + b.x + c.x) * k + bb.x, 0.0f);
    float v1 = fmaxf((a.y + b.y + c.y) * k + bb.y, 0.0f);
    float v2 = fmaxf((a.z + b.z + c.z) * k + bb.z, 0.0f);
    float v3 = fmaxf((a.w + b.w + c.w) * k + bb.w, 0.0f);
    __nv_bfloat16 h0 = __float2bfloat16(v0);
    __nv_bfloat16 h1 = __float2bfloat16(v1);
    __nv_bfloat16 h2 = __float2bfloat16(v2);
    __nv_bfloat16 h3 = __float2bfloat16(v3);
    __nv_bfloat16 l0 = __float2bfloat16(v0 - __bfloat162float(h0));
    __nv_bfloat16 l1 = __float2bfloat16(v1 - __bfloat162float(h1));
    __nv_bfloat16 l2 = __float2bfloat16(v2 - __bfloat162float(h2));
    __nv_bfloat16 l3 = __float2bfloat16(v3 - __bfloat162float(h3));
    size_t o = (size_t)f * DIMD + c4;
    *(uint2*)&g_A1H[o] = make_uint2(packbf2(h0, h1), packbf2(h2, h3));
    *(uint2*)&g_A1L[o] = make_uint2(packbf2(l0, l1), packbf2(l2, l3));
}

// ---------------------------------------------------------------------------
// out12 = (h3_hi + h3_lo) @ W4 + b4
// ---------------------------------------------------------------------------
__global__ __launch_bounds__(128)
void out12_kernel(const float* __restrict__ W4, const float* __restrict__ b4) {
    __shared__ float ws[256 * 12];
    for (int i = threadIdx.x; i < 256 * 12; i += blockDim.x) ws[i] = W4[i];
    __syncthreads();
    int r = blockIdx.x * blockDim.x + threadIdx.x;
    if (r >= N_FACES) return;
    const __nv_bfloat16* xh = g_H3H + (size_t)r * 256;
    const __nv_bfloat16* xl = g_H3L + (size_t)r * 256;
    float acc[12];
    #pragma unroll
    for (int n = 0; n < 12; n++) acc[n] = b4[n];
    for (int k = 0; k < 256; k += 8) {
        uint4 uh = *(const uint4*)&xh[k];
        uint4 ul = *(const uint4*)&xl[k];
        const uint32_t hu[4] = {uh.x, uh.y, uh.z, uh.w};
        const uint32_t lu[4] = {ul.x, ul.y, ul.z, ul.w};
        #pragma unroll
        for (int t = 0; t < 4; t++) {
            __nv_bfloat162 hb = *(const __nv_bfloat162*)&hu[t];
            __nv_bfloat162 lb = *(const __nv_bfloat162*)&lu[t];
            float v0 = __bfloat162float(hb.x) + __bfloat162float(lb.x);
            float v1 = __bfloat162float(hb.y) + __bfloat162float(lb.y);
            int kk = k + t * 2;
            #pragma unroll
            for (int n = 0; n < 12; n++) {
                acc[n] = fmaf(v0, ws[kk * 12 + n], acc[n]);
                acc[n] = fmaf(v1, ws[(kk + 1) * 12 + n], acc[n]);
            }
        }
    }
    #pragma unroll
    for (int n = 0; n < 12; n++) g_out12[(size_t)r * 12 + n] = acc[n];
}

// ---------------------------------------------------------------------------
// 3x3 Jacobi + special procrustes + transform + segment atomics
// ---------------------------------------------------------------------------
__device__ __forceinline__ void jrot(float A[3][3], float V[3][3],
                                     int p, int q, int r) {
    float apq = A[p][q];
    if (fabsf(apq) < 1e-20f) return;
    float tau = (A[q][q] - A[p][p]) / (2.0f * apq);
    float t = copysignf(1.0f, tau) / (fabsf(tau) + sqrtf(1.0f + tau * tau));
    float c = rsqrtf(1.0f + t * t);
    float s = t * c;
    A[p][p] -= t * apq;
    A[q][q] += t * apq;
    A[p][q] = 0.0f; A[q][p] = 0.0f;
    float arp = A[r][p], arq = A[r][q];
    A[r][p] = c * arp - s * arq; A[p][r] = A[r][p];
    A[r][q] = s * arp + c * arq; A[q][r] = A[r][q];
    #pragma unroll
    for (int k = 0; k < 3; k++) {
        float vkp = V[k][p], vkq = V[k][q];
        V[k][p] = c * vkp - s * vkq;
        V[k][q] = s * vkp + c * vkq;
    }
}

__device__ __forceinline__ void cross3(const float a[3], const float b[3], float o[3]) {
    o[0] = a[1] * b[2] - a[2] * b[1];
    o[1] = a[2] * b[0] - a[0] * b[2];
    o[2] = a[0] * b[1] - a[1] * b[0];
}

__global__ __launch_bounds__(256)
void procrustes_kernel(const float* __restrict__ verts,
                       const int*   __restrict__ faces,
                       float* __restrict__ out) {
    int f = blockIdx.x * blockDim.x + threadIdx.x;
    if (f >= N_FACES) return;

    float o[12];
    #pragma unroll
    for (int i = 0; i < 12; i++) o[i] = g_out12[(size_t)f * 12 + i];

    float m[3][3];
    #pragma unroll
    for (int i = 0; i < 3; i++)
        #pragma unroll
        for (int j = 0; j < 3; j++) m[i][j] = o[3 * i + j];

    float fr = 0.0f;
    #pragma unroll
    for (int i = 0; i < 3; i++)
        #pragma unroll
        for (int j = 0; j < 3; j++) fr += m[i][j] * m[i][j];
    float inv = rsqrtf(fmaxf(fr, 1e-30f));
    #pragma unroll
    for (int i = 0; i < 3; i++)
        #pragma unroll
        for (int j = 0; j < 3; j++) m[i][j] *= inv;

    float A[3][3];
    #pragma unroll
    for (int i = 0; i < 3; i++)
        #pragma unroll
        for (int j = 0; j < 3; j++) {
            float s = 0.0f;
            #pragma unroll
            for (int k = 0; k < 3; k++) s += m[k][i] * m[k][j];
            A[i][j] = s;
        }
    float V[3][3] = {{1,0,0},{0,1,0},{0,0,1}};

    #pragma unroll
    for (int sweep = 0; sweep < 6; sweep++) {
        jrot(A, V, 0, 1, 2);
        jrot(A, V, 0, 2, 1);
        jrot(A, V, 1, 2, 0);
    }

    float w0 = A[0][0], w1 = A[1][1], w2 = A[2][2];
    int imax = (w0 >= w1) ? (w0 >= w2 ? 0 : 2) : (w1 >= w2 ? 1 : 2);
    int imin = (w0 <= w1) ? (w0 <= w2 ? 0 : 2) : (w1 <= w2 ? 1 : 2);
    if (imax == imin) imin = (imax + 1) % 3;
    int imid = 3 - imax - imin;

    float v1[3] = {V[0][imax], V[1][imax], V[2][imax]};
    float v2[3] = {V[0][imid], V[1][imid], V[2][imid]};

    float u1[3], u2[3];
    #pragma unroll
    for (int a = 0; a < 3; a++)
        u1[a] = m[a][0] * v1[0] + m[a][1] * v1[1] + m[a][2] * v1[2];
    float n1 = sqrtf(u1[0]*u1[0] + u1[1]*u1[1] + u1[2]*u1[2]);
    if (n1 > 1e-12f) {
        float in1 = 1.0f / n1;
        u1[0] *= in1; u1[1] *= in1; u1[2] *= in1;
    } else { u1[0] = 1.0f; u1[1] = 0.0f; u1[2] = 0.0f; }

    #pragma unroll
    for (int a = 0; a < 3; a++)
        u2[a] = m[a][0] * v2[0] + m[a][1] * v2[1] + m[a][2] * v2[2];
    float d = u2[0]*u1[0] + u2[1]*u1[1] + u2[2]*u1[2];
    u2[0] -= d * u1[0]; u2[1] -= d * u1[1]; u2[2] -= d * u1[2];
    float n2 = sqrtf(u2[0]*u2[0] + u2[1]*u2[1] + u2[2]*u2[2]);
    if (n2 > 1e-10f) {
        float in2 = 1.0f / n2;
        u2[0] *= in2; u2[1] *= in2; u2[2] *= in2;
    } else {
        float e[3] = {0.f, 0.f, 0.f};
        e[(fabsf(u1[0]) < 0.9f) ? 0 : 1] = 1.0f;
        cross3(u1, e, u2);
        float nn = rsqrtf(fmaxf(u2[0]*u2[0]+u2[1]*u2[1]+u2[2]*u2[2], 1e-30f));
        u2[0] *= nn; u2[1] *= nn; u2[2] *= nn;
    }

    float u3[3], v3[3];
    cross3(u1, u2, u3);
    cross3(v1, v2, v3);

    float R[3][3];
    #pragma unroll
    for (int a = 0; a < 3; a++)
        #pragma unroll
        for (int b = 0; b < 3; b++)
            R[a][b] = u1[a]*v1[b] + u2[a]*v2[b] + u3[a]*v3[b];

    float* rot_out = out + (size_t)(N_VERTS * 3) + (size_t)N_FACES * 9 + (size_t)f * 9;
    #pragma unroll
    for (int a = 0; a < 3; a++)
        #pragma unroll
        for (int b = 0; b < 3; b++)
            rot_out[a * 3 + b] = R[a][b];

    float t0 = o[9], t1 = o[10], t2 = o[11];
    float* tp_out = out + (size_t)(N_VERTS * 3) + (size_t)f * 9;
    #pragma unroll
    for (int j = 0; j < 3; j++) {
        int vi = faces[f * 3 + j];
        float p0 = verts[(size_t)vi * 3 + 0];
        float p1 = verts[(size_t)vi * 3 + 1];
        float p2 = verts[(size_t)vi * 3 + 2];
        float tpx = p0 * R[0][0] + p1 * R[1][0] + p2 * R[2][0] + t0;
        float tpy = p0 * R[0][1] + p1 * R[1][1] + p2 * R[2][1] + t1;
        float tpz = p0 * R[0][2] + p1 * R[1][2] + p2 * R[2][2] + t2;
        tp_out[j * 3 + 0] = tpx;
        tp_out[j * 3 + 1] = tpy;
        tp_out[j * 3 + 2] = tpz;
        atomicAdd(&g_summed[(size_t)vi * 3 + 0], tpx);
        atomicAdd(&g_summed[(size_t)vi * 3 + 1], tpy);
        atomicAdd(&g_summed[(size_t)vi * 3 + 2], tpz);
        atomicAdd(&g_counts[vi], 1.0f);
    }
}

__global__ void finalize_kernel(float* __restrict__ out) {
    int v = blockIdx.x * blockDim.x + threadIdx.x;
    if (v >= N_VERTS) return;
    float c = fmaxf(g_counts[v], 1.0f);
    float ic = 1.0f / c;
    out[(size_t)v * 3 + 0] = g_summed[(size_t)v * 3 + 0] * ic;
    out[(size_t)v * 3 + 1] = g_summed[(size_t)v * 3 + 1] * ic;
    out[(size_t)v * 3 + 2] = g_summed[(size_t)v * 3 + 2] * ic;
}

// ---------------------------------------------------------------------------
extern "C" void kernel_launch(void* const* d_in, const int* in_sizes, int n_in,
                              void* d_out, int out_size) {
    const float* verts    = (const float*)d_in[0];
    const float* features = (const float*)d_in[1];
    const int*   faces    = (const int*)  d_in[2];
    const float* W1 = (const float*)d_in[3];
    const float* b1 = (const float*)d_in[4];
    const float* W2 = (const float*)d_in[5];
    const float* b2 = (const float*)d_in[6];
    const float* W3 = (const float*)d_in[7];
    const float* b3 = (const float*)d_in[8];
    const float* W4 = (const float*)d_in[9];
    const float* b4 = (const float*)d_in[10];
    float* out = (float*)d_out;

    (void)in_sizes; (void)n_in; (void)out_size;

    cudaFuncSetAttribute(gemm_mma_kernel,
                         cudaFuncAttributeMaxDynamicSharedMemorySize, GSMEM);

    zero_kernel<<<(N_VERTS * 3 + 255) / 256, 256>>>();

    convert_w<<<(512 * 512 + 255) / 256, 256>>>(W1, 8, 9, 512);
    convert_w<<<(512 * 512 + 255) / 256, 256>>>(W2, 10, 11, 512);
    convert_w<<<(256 * 512 + 255) / 256, 256>>>(W3, 12, 13, 256);

    split_feat_kernel<<<(N_VERTS * 128 + 255) / 256, 256>>>(features);

    // P = features @ W1t^T  (M = 100096, fp32 out, no bias)
    gemm_mma_kernel<<<dim3(4, MPAD1 / 128), 512, GSMEM>>>(
        0, 1, 8, 9, b1, 0, 0, 0, 512);

    // h1 = relu(mean3(P[faces]) + b1) -> bf16 hi/lo
    gather_mean_split_kernel<<<(N_FACES * 128 + 255) / 256, 256>>>(faces, b1);

    // h2 = relu(h1 @ W2t^T + b2) -> A2
    gemm_mma_kernel<<<dim3(4, MPAD / 128), 512, GSMEM>>>(
        2, 3, 10, 11, b2, 1, 4, 5, 512);

    // h3 = relu(h2 @ W3t^T + b3) -> H3
    gemm_mma_kernel<<<dim3(2, MPAD / 128), 512, GSMEM>>>(
        4, 5, 12, 13, b3, 1, 6, 7, 256);

    out12_kernel<<<(N_FACES + 127) / 128, 128>>>(W4, b4);

    procrustes_kernel<<<(N_FACES + 255) / 256, 256>>>(verts, faces, out);

    finalize_kernel<<<(N_VERTS + 255) / 256, 256>>>(out);
}

// round 8
// speedup vs baseline: 3.4178x; 1.1241x over previous
#include <cuda_runtime.h>
#include <cuda_bf16.h>
#include <cstdint>

// ===========================================================================
// PrismDecoder round 8: split-bf16 mma.sync GEMM, now 2 CTAs/SM
// (CTA tile 128x64, 48KB/stage, 2-stage) to overlap prologue/epilogue.
// Keeps layer-1 M-halving (P = features @ W1).
// ===========================================================================

#define N_VERTS 100000
#define N_FACES 200000
#define MPAD    200064            // 1563 * 128
#define MPAD1   100096            // 782  * 128
#define DIMD    512

// -------------------- static device scratch (zero-initialized) -------------
__device__ __nv_bfloat16 g_FH[(size_t)MPAD1 * 512];   // features hi
__device__ __nv_bfloat16 g_FL[(size_t)MPAD1 * 512];   // features lo
__device__ float         g_P [(size_t)MPAD1 * 512];   // features @ W1
__device__ __nv_bfloat16 g_A1H[(size_t)MPAD * 512];   // h1 hi
__device__ __nv_bfloat16 g_A1L[(size_t)MPAD * 512];
__device__ __nv_bfloat16 g_A2H[(size_t)MPAD * 512];   // h2 hi
__device__ __nv_bfloat16 g_A2L[(size_t)MPAD * 512];
__device__ __nv_bfloat16 g_H3H[(size_t)MPAD * 256];
__device__ __nv_bfloat16 g_H3L[(size_t)MPAD * 256];
// transposed weights [N][K] bf16 hi/lo
__device__ __nv_bfloat16 g_W1H[512 * 512];
__device__ __nv_bfloat16 g_W1L[512 * 512];
__device__ __nv_bfloat16 g_W2H[512 * 512];
__device__ __nv_bfloat16 g_W2L[512 * 512];
__device__ __nv_bfloat16 g_W3H[256 * 512];
__device__ __nv_bfloat16 g_W3L[256 * 512];
__device__ float g_out12[(size_t)N_FACES * 12];
__device__ float g_summed[(size_t)N_VERTS * 3];
__device__ float g_counts[N_VERTS];

__device__ __forceinline__ __nv_bfloat16* bsel(int s) {
    switch (s) {
        case 0:  return g_FH;   case 1:  return g_FL;
        case 2:  return g_A1H;  case 3:  return g_A1L;
        case 4:  return g_A2H;  case 5:  return g_A2L;
        case 6:  return g_H3H;  case 7:  return g_H3L;
        case 8:  return g_W1H;  case 9:  return g_W1L;
        case 10: return g_W2H;  case 11: return g_W2L;
        case 12: return g_W3H;  default: return g_W3L;
    }
}

// -------------------- PTX helpers (baseline ISA) ---------------------------
__device__ __forceinline__ uint32_t smem_u32(const void* p) {
    uint32_t a;
    asm("{ .reg .u64 t; cvta.to.shared.u64 t, %1; cvt.u32.u64 %0, t; }"
        : "=r"(a) : "l"(p));
    return a;
}
__device__ __forceinline__ void cp16(uint32_t dst, const void* src) {
    asm volatile("cp.async.cg.shared.global [%0], [%1], 16;"
                 :: "r"(dst), "l"(src));
}
#define CP_COMMIT() asm volatile("cp.async.commit_group;" ::: "memory")
#define CP_WAIT(n)  asm volatile("cp.async.wait_group %0;" :: "n"(n) : "memory")

__device__ __forceinline__ void ldmx4(uint32_t r[4], uint32_t addr) {
    asm volatile("ldmatrix.sync.aligned.m8n8.x4.shared.b16 {%0,%1,%2,%3}, [%4];"
                 : "=r"(r[0]), "=r"(r[1]), "=r"(r[2]), "=r"(r[3]) : "r"(addr));
}
__device__ __forceinline__ void ldmx2(uint32_t r[2], uint32_t addr) {
    asm volatile("ldmatrix.sync.aligned.m8n8.x2.shared.b16 {%0,%1}, [%2];"
                 : "=r"(r[0]), "=r"(r[1]) : "r"(addr));
}
__device__ __forceinline__ void mma16816(float d[4], const uint32_t a[4],
                                         const uint32_t b[2]) {
    asm volatile(
        "mma.sync.aligned.m16n8k16.row.col.f32.bf16.bf16.f32 "
        "{%0,%1,%2,%3}, {%4,%5,%6,%7}, {%8,%9}, {%0,%1,%2,%3};"
        : "+f"(d[0]), "+f"(d[1]), "+f"(d[2]), "+f"(d[3])
        : "r"(a[0]), "r"(a[1]), "r"(a[2]), "r"(a[3]), "r"(b[0]), "r"(b[1]));
}
__device__ __forceinline__ uint32_t packbf2(__nv_bfloat16 a, __nv_bfloat16 b) {
    return (uint32_t)__bfloat16_as_ushort(a) |
           ((uint32_t)__bfloat16_as_ushort(b) << 16);
}
#define SWZC(row, c16) ((uint32_t)((row) * 128 + (((c16) * 16) ^ (((row) & 7) * 16))))

// ---------------------------------------------------------------------------
__global__ void zero_kernel() {
    int i = blockIdx.x * blockDim.x + threadIdx.x;
    if (i < N_VERTS * 3) g_summed[i] = 0.0f;
    if (i < N_VERTS)     g_counts[i] = 0.0f;
}

// weight transpose + hi/lo split:  W [K][N] fp32 -> Wt [N][K] bf16 hi/lo
__global__ void convert_w(const float* __restrict__ W, int selH, int selL, int N) {
    int idx = blockIdx.x * blockDim.x + threadIdx.x;     // n*512 + k
    if (idx >= N * 512) return;
    int n = idx >> 9, k = idx & 511;
    float v = W[(size_t)k * N + n];
    __nv_bfloat16 h = __float2bfloat16(v);
    bsel(selH)[idx] = h;
    bsel(selL)[idx] = __float2bfloat16(v - __bfloat162float(h));
}

// features fp32 -> bf16 hi/lo (elementwise, no gather)
__global__ void split_feat_kernel(const float* __restrict__ features) {
    int idx = blockIdx.x * blockDim.x + threadIdx.x;      // float4 chunks
    if (idx >= N_VERTS * 128) return;
    size_t o = (size_t)idx * 4;
    float4 p = *(const float4*)&features[o];
    __nv_bfloat16 h0 = __float2bfloat16(p.x);
    __nv_bfloat16 h1 = __float2bfloat16(p.y);
    __nv_bfloat16 h2 = __float2bfloat16(p.z);
    __nv_bfloat16 h3 = __float2bfloat16(p.w);
    __nv_bfloat16 l0 = __float2bfloat16(p.x - __bfloat162float(h0));
    __nv_bfloat16 l1 = __float2bfloat16(p.y - __bfloat162float(h1));
    __nv_bfloat16 l2 = __float2bfloat16(p.z - __bfloat162float(h2));
    __nv_bfloat16 l3 = __float2bfloat16(p.w - __bfloat162float(h3));
    *(uint2*)&g_FH[o] = make_uint2(packbf2(h0, h1), packbf2(h2, h3));
    *(uint2*)&g_FL[o] = make_uint2(packbf2(l0, l1), packbf2(l2, l3));
}

// ---------------------------------------------------------------------------
// Split-bf16 HMMA GEMM: out = [relu](in[M,512] @ Wt[N,512]^T [+ bias])
// CTA tile 128(M)x64(N), 256 threads, 8 warps (4x2), warp tile 32x32.
// 2-stage cp.async pipeline, 48KB/stage -> 96KB/CTA -> 2 CTAs/SM.
// 3 MMA products per tile: Ah*Bh + Ah*Bl + Al*Bh.
// mode 0: fp32 out to g_P (no bias/relu).  mode 1: bias+relu+split bf16.
// ---------------------------------------------------------------------------
#define GSTAGE 49152              // Ah 16K | Al 16K | Bh 8K | Bl 8K
#define GSMEM  (2 * GSTAGE)

__global__ __launch_bounds__(256, 2)
void gemm_mma_kernel(int selInH, int selInL, int selWH, int selWL,
                     const float* __restrict__ bias, int mode,
                     int selOutH, int selOutL, int Ncols)
{
    extern __shared__ char smem[];
    const uint32_t sb = smem_u32(smem);
    const int tid  = threadIdx.x;
    const int lane = tid & 31;
    const int warp = tid >> 5;              // 0..7
    const int warpM = (warp >> 1) * 32;     // 0,32,64,96
    const int warpN = (warp & 1) * 32;      // 0,32
    const size_t mBase = (size_t)blockIdx.y * 128;
    const size_t nBase = (size_t)blockIdx.x * 64;

    const __nv_bfloat16* __restrict__ inH = bsel(selInH);
    const __nv_bfloat16* __restrict__ inL = bsel(selInL);
    const __nv_bfloat16* __restrict__ wH  = bsel(selWH);
    const __nv_bfloat16* __restrict__ wL  = bsel(selWL);

    // ldmatrix per-lane geometry (validated rounds 3/7)
    const int aRow   = (lane & 7) + ((lane >> 3) & 1) * 8;   // row within 16
    const int aColSl = lane >> 4;                            // 0/1 (16B col)
    const int bRow   = lane & 7;
    const int bColSl = (lane >> 3) & 1;

    float acc[2][4][4];
    #pragma unroll
    for (int i = 0; i < 2; i++)
        #pragma unroll
        for (int j = 0; j < 4; j++)
            #pragma unroll
            for (int q = 0; q < 4; q++) acc[i][j][q] = 0.0f;

    auto load_stage = [&](int c, int s) {
        uint32_t base = sb + s * GSTAGE;
        // A: 128 rows x 128B, hi + lo
        #pragma unroll
        for (int i = 0; i < 4; i++) {
            int ch = tid + i * 256;          // 0..1023
            int r = ch >> 3, c16 = ch & 7;
            uint32_t sw = SWZC(r, c16);
            size_t ga = (mBase + r) * 512 + (size_t)c * 64 + c16 * 8;
            cp16(base + sw,         inH + ga);
            cp16(base + 16384 + sw, inL + ga);
        }
        // B: 64 rows x 128B, hi + lo
        #pragma unroll
        for (int i = 0; i < 2; i++) {
            int ch = tid + i * 256;          // 0..511
            int r = ch >> 3, c16 = ch & 7;
            uint32_t sw = SWZC(r, c16);
            size_t gb = (nBase + r) * 512 + (size_t)c * 64 + c16 * 8;
            cp16(base + 32768 + sw, wH + gb);
            cp16(base + 40960 + sw, wL + gb);
        }
        CP_COMMIT();
    };

    load_stage(0, 0);
    load_stage(1, 1);

    #pragma unroll 1
    for (int c = 0; c < 8; c++) {
        if (c < 7) { CP_WAIT(1); } else { CP_WAIT(0); }
        __syncthreads();

        const uint32_t aBh = sb + (c & 1) * GSTAGE;
        const uint32_t aBl = aBh + 16384;
        const uint32_t bBh = aBh + 32768;
        const uint32_t bBl = aBh + 40960;

        #pragma unroll
        for (int ks = 0; ks < 4; ks++) {
            uint32_t ah[2][4], al[2][4];
            const int cA = ks * 2 + aColSl;
            #pragma unroll
            for (int i = 0; i < 2; i++) {
                int row = warpM + i * 16 + aRow;
                uint32_t off = SWZC(row, cA);
                ldmx4(ah[i], aBh + off);
                ldmx4(al[i], aBl + off);
            }
            uint32_t bh[4][2], bl[4][2];
            const int cB = ks * 2 + bColSl;
            #pragma unroll
            for (int j = 0; j < 4; j++) {
                int row = warpN + j * 8 + bRow;
                uint32_t off = SWZC(row, cB);
                ldmx2(bh[j], bBh + off);
                ldmx2(bl[j], bBl + off);
            }
            #pragma unroll
            for (int i = 0; i < 2; i++)
                #pragma unroll
                for (int j = 0; j < 4; j++) {
                    mma16816(acc[i][j], ah[i], bh[j]);
                    mma16816(acc[i][j], ah[i], bl[j]);
                    mma16816(acc[i][j], al[i], bh[j]);
                }
        }

        if (c + 2 < 8) {
            __syncthreads();           // all reads of stage (c&1) complete
            load_stage(c + 2, c & 1);
        }
    }

    // ---- epilogue ----
    const int colq = (lane & 3) * 2;
    const int rowq = lane >> 2;

    if (mode == 0) {
        float* __restrict__ P = g_P;
        #pragma unroll
        for (int j = 0; j < 4; j++) {
            size_t col = nBase + warpN + j * 8 + colq;
            #pragma unroll
            for (int i = 0; i < 2; i++) {
                size_t row0 = mBase + warpM + i * 16 + rowq;
                *(float2*)&P[row0 * 512 + col] =
                    make_float2(acc[i][j][0], acc[i][j][1]);
                *(float2*)&P[(row0 + 8) * 512 + col] =
                    make_float2(acc[i][j][2], acc[i][j][3]);
            }
        }
        return;
    }

    __nv_bfloat16* __restrict__ oH = bsel(selOutH);
    __nv_bfloat16* __restrict__ oL = bsel(selOutL);
    #pragma unroll
    for (int j = 0; j < 4; j++) {
        size_t col = nBase + warpN + j * 8 + colq;
        float b0 = __ldg(&bias[col]);
        float b1 = __ldg(&bias[col + 1]);
        #pragma unroll
        for (int i = 0; i < 2; i++) {
            size_t row0 = mBase + warpM + i * 16 + rowq;
            size_t row1 = row0 + 8;
            float v00 = fmaxf(acc[i][j][0] + b0, 0.0f);
            float v01 = fmaxf(acc[i][j][1] + b1, 0.0f);
            float v10 = fmaxf(acc[i][j][2] + b0, 0.0f);
            float v11 = fmaxf(acc[i][j][3] + b1, 0.0f);
            __nv_bfloat16 h00 = __float2bfloat16(v00);
            __nv_bfloat16 h01 = __float2bfloat16(v01);
            __nv_bfloat16 h10 = __float2bfloat16(v10);
            __nv_bfloat16 h11 = __float2bfloat16(v11);
            __nv_bfloat16 l00 = __float2bfloat16(v00 - __bfloat162float(h00));
            __nv_bfloat16 l01 = __float2bfloat16(v01 - __bfloat162float(h01));
            __nv_bfloat16 l10 = __float2bfloat16(v10 - __bfloat162float(h10));
            __nv_bfloat16 l11 = __float2bfloat16(v11 - __bfloat162float(h11));
            *(uint32_t*)&oH[row0 * Ncols + col] = packbf2(h00, h01);
            *(uint32_t*)&oH[row1 * Ncols + col] = packbf2(h10, h11);
            *(uint32_t*)&oL[row0 * Ncols + col] = packbf2(l00, l01);
            *(uint32_t*)&oL[row1 * Ncols + col] = packbf2(l10, l11);
        }
    }
}

// ---------------------------------------------------------------------------
// h1 = relu(mean3(P[faces]) + b1) -> bf16 hi/lo.
// one thread per (face, float4-chunk); 128 chunks per face.
// ---------------------------------------------------------------------------
__global__ void gather_mean_split_kernel(const int* __restrict__ faces,
                                         const float* __restrict__ b1) {
    int idx = blockIdx.x * blockDim.x + threadIdx.x;
    int f  = idx >> 7;
    int c4 = (idx & 127) << 2;
    if (f >= N_FACES) return;
    int i0 = __ldg(&faces[f * 3 + 0]);
    int i1 = __ldg(&faces[f * 3 + 1]);
    int i2 = __ldg(&faces[f * 3 + 2]);
    float4 a = *(const float4*)&g_P[(size_t)i0 * DIMD + c4];
    float4 b = *(const float4*)&g_P[(size_t)i1 * DIMD + c4];
    float4 c = *(const float4*)&g_P[(size_t)i2 * DIMD + c4];
    float4 bb = *(const float4*)&b1[c4];
    const float k = 1.0f / 3.0f;
    float v0 = fmaxf((a.x + b.x + c.x) * k + bb.x, 0.0f);
    float v1 = fmaxf((a.y + b.y + c.y) * k + bb.y, 0.0f);
    float v2 = fmaxf((a.z + b.z + c.z) * k + bb.z, 0.0f);
    float v3 = fmaxf((a.w + b.w + c.w) * k + bb.w, 0.0f);
    __nv_bfloat16 h0 = __float2bfloat16(v0);
    __nv_bfloat16 h1 = __float2bfloat16(v1);
    __nv_bfloat16 h2 = __float2bfloat16(v2);
    __nv_bfloat16 h3 = __float2bfloat16(v3);
    __nv_bfloat16 l0 = __float2bfloat16(v0 - __bfloat162float(h0));
    __nv_bfloat16 l1 = __float2bfloat16(v1 - __bfloat162float(h1));
    __nv_bfloat16 l2 = __float2bfloat16(v2 - __bfloat162float(h2));
    __nv_bfloat16 l3 = __float2bfloat16(v3 - __bfloat162float(h3));
    size_t o = (size_t)f * DIMD + c4;
    *(uint2*)&g_A1H[o] = make_uint2(packbf2(h0, h1), packbf2(h2, h3));
    *(uint2*)&g_A1L[o] = make_uint2(packbf2(l0, l1), packbf2(l2, l3));
}

// ---------------------------------------------------------------------------
// out12 = (h3_hi + h3_lo) @ W4 + b4
// ---------------------------------------------------------------------------
__global__ __launch_bounds__(128)
void out12_kernel(const float* __restrict__ W4, const float* __restrict__ b4) {
    __shared__ float ws[256 * 12];
    for (int i = threadIdx.x; i < 256 * 12; i += blockDim.x) ws[i] = W4[i];
    __syncthreads();
    int r = blockIdx.x * blockDim.x + threadIdx.x;
    if (r >= N_FACES) return;
    const __nv_bfloat16* xh = g_H3H + (size_t)r * 256;
    const __nv_bfloat16* xl = g_H3L + (size_t)r * 256;
    float acc[12];
    #pragma unroll
    for (int n = 0; n < 12; n++) acc[n] = b4[n];
    for (int k = 0; k < 256; k += 8) {
        uint4 uh = *(const uint4*)&xh[k];
        uint4 ul = *(const uint4*)&xl[k];
        const uint32_t hu[4] = {uh.x, uh.y, uh.z, uh.w};
        const uint32_t lu[4] = {ul.x, ul.y, ul.z, ul.w};
        #pragma unroll
        for (int t = 0; t < 4; t++) {
            __nv_bfloat162 hb = *(const __nv_bfloat162*)&hu[t];
            __nv_bfloat162 lb = *(const __nv_bfloat162*)&lu[t];
            float v0 = __bfloat162float(hb.x) + __bfloat162float(lb.x);
            float v1 = __bfloat162float(hb.y) + __bfloat162float(lb.y);
            int kk = k + t * 2;
            #pragma unroll
            for (int n = 0; n < 12; n++) {
                acc[n] = fmaf(v0, ws[kk * 12 + n], acc[n]);
                acc[n] = fmaf(v1, ws[(kk + 1) * 12 + n], acc[n]);
            }
        }
    }
    #pragma unroll
    for (int n = 0; n < 12; n++) g_out12[(size_t)r * 12 + n] = acc[n];
}

// ---------------------------------------------------------------------------
// 3x3 Jacobi + special procrustes + transform + segment atomics
// ---------------------------------------------------------------------------
__device__ __forceinline__ void jrot(float A[3][3], float V[3][3],
                                     int p, int q, int r) {
    float apq = A[p][q];
    if (fabsf(apq) < 1e-20f) return;
    float tau = (A[q][q] - A[p][p]) / (2.0f * apq);
    float t = copysignf(1.0f, tau) / (fabsf(tau) + sqrtf(1.0f + tau * tau));
    float c = rsqrtf(1.0f + t * t);
    float s = t * c;
    A[p][p] -= t * apq;
    A[q][q] += t * apq;
    A[p][q] = 0.0f; A[q][p] = 0.0f;
    float arp = A[r][p], arq = A[r][q];
    A[r][p] = c * arp - s * arq; A[p][r] = A[r][p];
    A[r][q] = s * arp + c * arq; A[q][r] = A[r][q];
    #pragma unroll
    for (int k = 0; k < 3; k++) {
        float vkp = V[k][p], vkq = V[k][q];
        V[k][p] = c * vkp - s * vkq;
        V[k][q] = s * vkp + c * vkq;
    }
}

__device__ __forceinline__ void cross3(const float a[3], const float b[3], float o[3]) {
    o[0] = a[1] * b[2] - a[2] * b[1];
    o[1] = a[2] * b[0] - a[0] * b[2];
    o[2] = a[0] * b[1] - a[1] * b[0];
}

__global__ __launch_bounds__(256)
void procrustes_kernel(const float* __restrict__ verts,
                       const int*   __restrict__ faces,
                       float* __restrict__ out) {
    int f = blockIdx.x * blockDim.x + threadIdx.x;
    if (f >= N_FACES) return;

    float o[12];
    #pragma unroll
    for (int i = 0; i < 12; i++) o[i] = g_out12[(size_t)f * 12 + i];

    float m[3][3];
    #pragma unroll
    for (int i = 0; i < 3; i++)
        #pragma unroll
        for (int j = 0; j < 3; j++) m[i][j] = o[3 * i + j];

    float fr = 0.0f;
    #pragma unroll
    for (int i = 0; i < 3; i++)
        #pragma unroll
        for (int j = 0; j < 3; j++) fr += m[i][j] * m[i][j];
    float inv = rsqrtf(fmaxf(fr, 1e-30f));
    #pragma unroll
    for (int i = 0; i < 3; i++)
        #pragma unroll
        for (int j = 0; j < 3; j++) m[i][j] *= inv;

    float A[3][3];
    #pragma unroll
    for (int i = 0; i < 3; i++)
        #pragma unroll
        for (int j = 0; j < 3; j++) {
            float s = 0.0f;
            #pragma unroll
            for (int k = 0; k < 3; k++) s += m[k][i] * m[k][j];
            A[i][j] = s;
        }
    float V[3][3] = {{1,0,0},{0,1,0},{0,0,1}};

    #pragma unroll
    for (int sweep = 0; sweep < 6; sweep++) {
        jrot(A, V, 0, 1, 2);
        jrot(A, V, 0, 2, 1);
        jrot(A, V, 1, 2, 0);
    }

    float w0 = A[0][0], w1 = A[1][1], w2 = A[2][2];
    int imax = (w0 >= w1) ? (w0 >= w2 ? 0 : 2) : (w1 >= w2 ? 1 : 2);
    int imin = (w0 <= w1) ? (w0 <= w2 ? 0 : 2) : (w1 <= w2 ? 1 : 2);
    if (imax == imin) imin = (imax + 1) % 3;
    int imid = 3 - imax - imin;

    float v1[3] = {V[0][imax], V[1][imax], V[2][imax]};
    float v2[3] = {V[0][imid], V[1][imid], V[2][imid]};

    float u1[3], u2[3];
    #pragma unroll
    for (int a = 0; a < 3; a++)
        u1[a] = m[a][0] * v1[0] + m[a][1] * v1[1] + m[a][2] * v1[2];
    float n1 = sqrtf(u1[0]*u1[0] + u1[1]*u1[1] + u1[2]*u1[2]);
    if (n1 > 1e-12f) {
        float in1 = 1.0f / n1;
        u1[0] *= in1; u1[1] *= in1; u1[2] *= in1;
    } else { u1[0] = 1.0f; u1[1] = 0.0f; u1[2] = 0.0f; }

    #pragma unroll
    for (int a = 0; a < 3; a++)
        u2[a] = m[a][0] * v2[0] + m[a][1] * v2[1] + m[a][2] * v2[2];
    float d = u2[0]*u1[0] + u2[1]*u1[1] + u2[2]*u1[2];
    u2[0] -= d * u1[0]; u2[1] -= d * u1[1]; u2[2] -= d * u1[2];
    float n2 = sqrtf(u2[0]*u2[0] + u2[1]*u2[1] + u2[2]*u2[2]);
    if (n2 > 1e-10f) {
        float in2 = 1.0f / n2;
        u2[0] *= in2; u2[1] *= in2; u2[2] *= in2;
    } else {
        float e[3] = {0.f, 0.f, 0.f};
        e[(fabsf(u1[0]) < 0.9f) ? 0 : 1] = 1.0f;
        cross3(u1, e, u2);
        float nn = rsqrtf(fmaxf(u2[0]*u2[0]+u2[1]*u2[1]+u2[2]*u2[2], 1e-30f));
        u2[0] *= nn; u2[1] *= nn; u2[2] *= nn;
    }

    float u3[3], v3[3];
    cross3(u1, u2, u3);
    cross3(v1, v2, v3);

    float R[3][3];
    #pragma unroll
    for (int a = 0; a < 3; a++)
        #pragma unroll
        for (int b = 0; b < 3; b++)
            R[a][b] = u1[a]*v1[b] + u2[a]*v2[b] + u3[a]*v3[b];

    float* rot_out = out + (size_t)(N_VERTS * 3) + (size_t)N_FACES * 9 + (size_t)f * 9;
    #pragma unroll
    for (int a = 0; a < 3; a++)
        #pragma unroll
        for (int b = 0; b < 3; b++)
            rot_out[a * 3 + b] = R[a][b];

    float t0 = o[9], t1 = o[10], t2 = o[11];
    float* tp_out = out + (size_t)(N_VERTS * 3) + (size_t)f * 9;
    #pragma unroll
    for (int j = 0; j < 3; j++) {
        int vi = faces[f * 3 + j];
        float p0 = verts[(size_t)vi * 3 + 0];
        float p1 = verts[(size_t)vi * 3 + 1];
        float p2 = verts[(size_t)vi * 3 + 2];
        float tpx = p0 * R[0][0] + p1 * R[1][0] + p2 * R[2][0] + t0;
        float tpy = p0 * R[0][1] + p1 * R[1][1] + p2 * R[2][1] + t1;
        float tpz = p0 * R[0][2] + p1 * R[1][2] + p2 * R[2][2] + t2;
        tp_out[j * 3 + 0] = tpx;
        tp_out[j * 3 + 1] = tpy;
        tp_out[j * 3 + 2] = tpz;
        atomicAdd(&g_summed[(size_t)vi * 3 + 0], tpx);
        atomicAdd(&g_summed[(size_t)vi * 3 + 1], tpy);
        atomicAdd(&g_summed[(size_t)vi * 3 + 2], tpz);
        atomicAdd(&g_counts[vi], 1.0f);
    }
}

__global__ void finalize_kernel(float* __restrict__ out) {
    int v = blockIdx.x * blockDim.x + threadIdx.x;
    if (v >= N_VERTS) return;
    float c = fmaxf(g_counts[v], 1.0f);
    float ic = 1.0f / c;
    out[(size_t)v * 3 + 0] = g_summed[(size_t)v * 3 + 0] * ic;
    out[(size_t)v * 3 + 1] = g_summed[(size_t)v * 3 + 1] * ic;
    out[(size_t)v * 3 + 2] = g_summed[(size_t)v * 3 + 2] * ic;
}

// ---------------------------------------------------------------------------
extern "C" void kernel_launch(void* const* d_in, const int* in_sizes, int n_in,
                              void* d_out, int out_size) {
    const float* verts    = (const float*)d_in[0];
    const float* features = (const float*)d_in[1];
    const int*   faces    = (const int*)  d_in[2];
    const float* W1 = (const float*)d_in[3];
    const float* b1 = (const float*)d_in[4];
    const float* W2 = (const float*)d_in[5];
    const float* b2 = (const float*)d_in[6];
    const float* W3 = (const float*)d_in[7];
    const float* b3 = (const float*)d_in[8];
    const float* W4 = (const float*)d_in[9];
    const float* b4 = (const float*)d_in[10];
    float* out = (float*)d_out;

    (void)in_sizes; (void)n_in; (void)out_size;

    cudaFuncSetAttribute(gemm_mma_kernel,
                         cudaFuncAttributeMaxDynamicSharedMemorySize, GSMEM);

    zero_kernel<<<(N_VERTS * 3 + 255) / 256, 256>>>();

    convert_w<<<(512 * 512 + 255) / 256, 256>>>(W1, 8, 9, 512);
    convert_w<<<(512 * 512 + 255) / 256, 256>>>(W2, 10, 11, 512);
    convert_w<<<(256 * 512 + 255) / 256, 256>>>(W3, 12, 13, 256);

    split_feat_kernel<<<(N_VERTS * 128 + 255) / 256, 256>>>(features);

    // P = features @ W1t^T  (M = 100096, fp32 out, no bias)
    gemm_mma_kernel<<<dim3(8, MPAD1 / 128), 256, GSMEM>>>(
        0, 1, 8, 9, b1, 0, 0, 0, 512);

    // h1 = relu(mean3(P[faces]) + b1) -> bf16 hi/lo
    gather_mean_split_kernel<<<(N_FACES * 128 + 255) / 256, 256>>>(faces, b1);

    // h2 = relu(h1 @ W2t^T + b2) -> A2
    gemm_mma_kernel<<<dim3(8, MPAD / 128), 256, GSMEM>>>(
        2, 3, 10, 11, b2, 1, 4, 5, 512);

    // h3 = relu(h2 @ W3t^T + b3) -> H3
    gemm_mma_kernel<<<dim3(4, MPAD / 128), 256, GSMEM>>>(
        4, 5, 12, 13, b3, 1, 6, 7, 256);

    out12_kernel<<<(N_FACES + 127) / 128, 128>>>(W4, b4);

    procrustes_kernel<<<(N_FACES + 255) / 256, 256>>>(verts, faces, out);

    finalize_kernel<<<(N_VERTS + 255) / 256, 256>>>(out);
}

// round 9
// speedup vs baseline: 3.4786x; 1.0178x over previous
#include <cuda_runtime.h>
#include <cuda_bf16.h>
#include <cstdint>

// ===========================================================================
// PrismDecoder round 9: persistent-CTA split-bf16 mma.sync GEMM with
// cross-tile software pipelining (epilogue + next-tile prologue hidden),
// B fragments via ldmatrix.x4. 2 CTAs/SM. Layer-1 M-halving kept.
// ===========================================================================

#define N_VERTS 100000
#define N_FACES 200000
#define MPAD    200064            // 1563 * 128
#define MPAD1   100096            // 782  * 128
#define DIMD    512
#define GRID_P  304               // 2 x 152 SMs

// -------------------- static device scratch (zero-initialized) -------------
__device__ __nv_bfloat16 g_FH[(size_t)MPAD1 * 512];   // features hi
__device__ __nv_bfloat16 g_FL[(size_t)MPAD1 * 512];   // features lo
__device__ float         g_P [(size_t)MPAD1 * 512];   // features @ W1
__device__ __nv_bfloat16 g_A1H[(size_t)MPAD * 512];   // h1 hi
__device__ __nv_bfloat16 g_A1L[(size_t)MPAD * 512];
__device__ __nv_bfloat16 g_A2H[(size_t)MPAD * 512];   // h2 hi
__device__ __nv_bfloat16 g_A2L[(size_t)MPAD * 512];
__device__ __nv_bfloat16 g_H3H[(size_t)MPAD * 256];
__device__ __nv_bfloat16 g_H3L[(size_t)MPAD * 256];
// transposed weights [N][K] bf16 hi/lo
__device__ __nv_bfloat16 g_W1H[512 * 512];
__device__ __nv_bfloat16 g_W1L[512 * 512];
__device__ __nv_bfloat16 g_W2H[512 * 512];
__device__ __nv_bfloat16 g_W2L[512 * 512];
__device__ __nv_bfloat16 g_W3H[256 * 512];
__device__ __nv_bfloat16 g_W3L[256 * 512];
__device__ float g_out12[(size_t)N_FACES * 12];
__device__ float g_summed[(size_t)N_VERTS * 3];
__device__ float g_counts[N_VERTS];

__device__ __forceinline__ __nv_bfloat16* bsel(int s) {
    switch (s) {
        case 0:  return g_FH;   case 1:  return g_FL;
        case 2:  return g_A1H;  case 3:  return g_A1L;
        case 4:  return g_A2H;  case 5:  return g_A2L;
        case 6:  return g_H3H;  case 7:  return g_H3L;
        case 8:  return g_W1H;  case 9:  return g_W1L;
        case 10: return g_W2H;  case 11: return g_W2L;
        case 12: return g_W3H;  default: return g_W3L;
    }
}

// -------------------- PTX helpers (baseline ISA) ---------------------------
__device__ __forceinline__ uint32_t smem_u32(const void* p) {
    uint32_t a;
    asm("{ .reg .u64 t; cvta.to.shared.u64 t, %1; cvt.u32.u64 %0, t; }"
        : "=r"(a) : "l"(p));
    return a;
}
__device__ __forceinline__ void cp16(uint32_t dst, const void* src) {
    asm volatile("cp.async.cg.shared.global [%0], [%1], 16;"
                 :: "r"(dst), "l"(src));
}
#define CP_COMMIT() asm volatile("cp.async.commit_group;" ::: "memory")
#define CP_WAIT(n)  asm volatile("cp.async.wait_group %0;" :: "n"(n) : "memory")

__device__ __forceinline__ void ldmx4(uint32_t r[4], uint32_t addr) {
    asm volatile("ldmatrix.sync.aligned.m8n8.x4.shared.b16 {%0,%1,%2,%3}, [%4];"
                 : "=r"(r[0]), "=r"(r[1]), "=r"(r[2]), "=r"(r[3]) : "r"(addr));
}
__device__ __forceinline__ void ldmx4p(uint32_t& r0, uint32_t& r1,
                                       uint32_t& r2, uint32_t& r3,
                                       uint32_t addr) {
    asm volatile("ldmatrix.sync.aligned.m8n8.x4.shared.b16 {%0,%1,%2,%3}, [%4];"
                 : "=r"(r0), "=r"(r1), "=r"(r2), "=r"(r3) : "r"(addr));
}
__device__ __forceinline__ void mma16816(float d[4], const uint32_t a[4],
                                         const uint32_t b[2]) {
    asm volatile(
        "mma.sync.aligned.m16n8k16.row.col.f32.bf16.bf16.f32 "
        "{%0,%1,%2,%3}, {%4,%5,%6,%7}, {%8,%9}, {%0,%1,%2,%3};"
        : "+f"(d[0]), "+f"(d[1]), "+f"(d[2]), "+f"(d[3])
        : "r"(a[0]), "r"(a[1]), "r"(a[2]), "r"(a[3]), "r"(b[0]), "r"(b[1]));
}
__device__ __forceinline__ uint32_t packbf2(__nv_bfloat16 a, __nv_bfloat16 b) {
    return (uint32_t)__bfloat16_as_ushort(a) |
           ((uint32_t)__bfloat16_as_ushort(b) << 16);
}
#define SWZC(row, c16) ((uint32_t)((row) * 128 + (((c16) * 16) ^ (((row) & 7) * 16))))

// ---------------------------------------------------------------------------
__global__ void zero_kernel() {
    int i = blockIdx.x * blockDim.x + threadIdx.x;
    if (i < N_VERTS * 3) g_summed[i] = 0.0f;
    if (i < N_VERTS)     g_counts[i] = 0.0f;
}

// weight transpose + hi/lo split:  W [K][N] fp32 -> Wt [N][K] bf16 hi/lo
__global__ void convert_w(const float* __restrict__ W, int selH, int selL, int N) {
    int idx = blockIdx.x * blockDim.x + threadIdx.x;     // n*512 + k
    if (idx >= N * 512) return;
    int n = idx >> 9, k = idx & 511;
    float v = W[(size_t)k * N + n];
    __nv_bfloat16 h = __float2bfloat16(v);
    bsel(selH)[idx] = h;
    bsel(selL)[idx] = __float2bfloat16(v - __bfloat162float(h));
}

// features fp32 -> bf16 hi/lo (elementwise, no gather)
__global__ void split_feat_kernel(const float* __restrict__ features) {
    int idx = blockIdx.x * blockDim.x + threadIdx.x;      // float4 chunks
    if (idx >= N_VERTS * 128) return;
    size_t o = (size_t)idx * 4;
    float4 p = *(const float4*)&features[o];
    __nv_bfloat16 h0 = __float2bfloat16(p.x);
    __nv_bfloat16 h1 = __float2bfloat16(p.y);
    __nv_bfloat16 h2 = __float2bfloat16(p.z);
    __nv_bfloat16 h3 = __float2bfloat16(p.w);
    __nv_bfloat16 l0 = __float2bfloat16(p.x - __bfloat162float(h0));
    __nv_bfloat16 l1 = __float2bfloat16(p.y - __bfloat162float(h1));
    __nv_bfloat16 l2 = __float2bfloat16(p.z - __bfloat162float(h2));
    __nv_bfloat16 l3 = __float2bfloat16(p.w - __bfloat162float(h3));
    *(uint2*)&g_FH[o] = make_uint2(packbf2(h0, h1), packbf2(h2, h3));
    *(uint2*)&g_FL[o] = make_uint2(packbf2(l0, l1), packbf2(l2, l3));
}

// ---------------------------------------------------------------------------
// Persistent split-bf16 HMMA GEMM: out = [relu](in[M,512] @ Wt[N,512]^T [+b])
// CTA tile 128(M)x64(N), 256 threads, 8 warps (4x2), warp tile 32x32.
// 2-stage cp.async pipeline runs continuously across tiles; epilogue issues
// after next-tile loads so it is hidden. 48KB/stage -> 2 CTAs/SM.
// 3 MMA products per k-tile: Ah*Bh + Ah*Bl + Al*Bh.
// mode 0: fp32 out to g_P.  mode 1: bias+relu+split bf16.
// ---------------------------------------------------------------------------
#define GSTAGE 49152              // Ah 16K | Al 16K | Bh 8K | Bl 8K
#define GSMEM  (2 * GSTAGE)

__global__ __launch_bounds__(256, 2)
void gemm_mma_persist(int selInH, int selInL, int selWH, int selWL,
                      const float* __restrict__ bias, int mode,
                      int selOutH, int selOutL, int Ncols,
                      int nBlk, int numTiles)
{
    extern __shared__ char smem[];
    const uint32_t sb = smem_u32(smem);
    const int tid  = threadIdx.x;
    const int lane = tid & 31;
    const int warp = tid >> 5;              // 0..7
    const int warpM = (warp >> 1) * 32;     // 0,32,64,96
    const int warpN = (warp & 1) * 32;      // 0,32

    const __nv_bfloat16* __restrict__ inH = bsel(selInH);
    const __nv_bfloat16* __restrict__ inL = bsel(selInL);
    const __nv_bfloat16* __restrict__ wH  = bsel(selWH);
    const __nv_bfloat16* __restrict__ wL  = bsel(selWL);

    // number of tiles owned by this CTA
    const int nMine = (numTiles - blockIdx.x + gridDim.x - 1) / gridDim.x;
    if (nMine <= 0) return;
    const int total = nMine * 8;            // chunk stream length

    // ldmatrix per-lane geometry (validated rounds 3/7/8)
    const int aRow   = (lane & 7) + ((lane >> 3) & 1) * 8;   // row within 16
    const int aColSl = lane >> 4;                            // 0/1 (16B col)
    const int bg     = lane >> 3;                            // 0..3 (x4 group)
    const int bgRow  = lane & 7;

    float acc[2][4][4];
    #pragma unroll
    for (int i = 0; i < 2; i++)
        #pragma unroll
        for (int j = 0; j < 4; j++)
            #pragma unroll
            for (int q = 0; q < 4; q++) acc[i][j][q] = 0.0f;

    auto tile_coords = [&](int q, size_t& mB, size_t& nB) {
        int t = blockIdx.x + q * gridDim.x;
        mB = (size_t)(t / nBlk) * 128;
        nB = (size_t)(t % nBlk) * 64;
    };

    auto load_chunk = [&](int s, int stage) {
        int q = s >> 3, c = s & 7;
        size_t mBase, nBase;
        tile_coords(q, mBase, nBase);
        uint32_t base = sb + stage * GSTAGE;
        // A: 128 rows x 128B, hi + lo
        #pragma unroll
        for (int i = 0; i < 4; i++) {
            int ch = tid + i * 256;          // 0..1023
            int r = ch >> 3, c16 = ch & 7;
            uint32_t sw = SWZC(r, c16);
            size_t ga = (mBase + r) * 512 + (size_t)c * 64 + c16 * 8;
            cp16(base + sw,         inH + ga);
            cp16(base + 16384 + sw, inL + ga);
        }
        // B: 64 rows x 128B, hi + lo
        #pragma unroll
        for (int i = 0; i < 2; i++) {
            int ch = tid + i * 256;          // 0..511
            int r = ch >> 3, c16 = ch & 7;
            uint32_t sw = SWZC(r, c16);
            size_t gb = (nBase + r) * 512 + (size_t)c * 64 + c16 * 8;
            cp16(base + 32768 + sw, wH + gb);
            cp16(base + 40960 + sw, wL + gb);
        }
        CP_COMMIT();
    };

    auto epilogue = [&](int q) {
        size_t mBase, nBase;
        tile_coords(q, mBase, nBase);
        const int colq = (lane & 3) * 2;
        const int rowq = lane >> 2;
        if (mode == 0) {
            float* __restrict__ P = g_P;
            #pragma unroll
            for (int j = 0; j < 4; j++) {
                size_t col = nBase + warpN + j * 8 + colq;
                #pragma unroll
                for (int i = 0; i < 2; i++) {
                    size_t row0 = mBase + warpM + i * 16 + rowq;
                    *(float2*)&P[row0 * 512 + col] =
                        make_float2(acc[i][j][0], acc[i][j][1]);
                    *(float2*)&P[(row0 + 8) * 512 + col] =
                        make_float2(acc[i][j][2], acc[i][j][3]);
                }
            }
        } else {
            __nv_bfloat16* __restrict__ oH = bsel(selOutH);
            __nv_bfloat16* __restrict__ oL = bsel(selOutL);
            #pragma unroll
            for (int j = 0; j < 4; j++) {
                size_t col = nBase + warpN + j * 8 + colq;
                float b0 = __ldg(&bias[col]);
                float b1 = __ldg(&bias[col + 1]);
                #pragma unroll
                for (int i = 0; i < 2; i++) {
                    size_t row0 = mBase + warpM + i * 16 + rowq;
                    size_t row1 = row0 + 8;
                    float v00 = fmaxf(acc[i][j][0] + b0, 0.0f);
                    float v01 = fmaxf(acc[i][j][1] + b1, 0.0f);
                    float v10 = fmaxf(acc[i][j][2] + b0, 0.0f);
                    float v11 = fmaxf(acc[i][j][3] + b1, 0.0f);
                    __nv_bfloat16 h00 = __float2bfloat16(v00);
                    __nv_bfloat16 h01 = __float2bfloat16(v01);
                    __nv_bfloat16 h10 = __float2bfloat16(v10);
                    __nv_bfloat16 h11 = __float2bfloat16(v11);
                    __nv_bfloat16 l00 = __float2bfloat16(v00 - __bfloat162float(h00));
                    __nv_bfloat16 l01 = __float2bfloat16(v01 - __bfloat162float(h01));
                    __nv_bfloat16 l10 = __float2bfloat16(v10 - __bfloat162float(h10));
                    __nv_bfloat16 l11 = __float2bfloat16(v11 - __bfloat162float(h11));
                    *(uint32_t*)&oH[row0 * Ncols + col] = packbf2(h00, h01);
                    *(uint32_t*)&oH[row1 * Ncols + col] = packbf2(h10, h11);
                    *(uint32_t*)&oL[row0 * Ncols + col] = packbf2(l00, l01);
                    *(uint32_t*)&oL[row1 * Ncols + col] = packbf2(l10, l11);
                }
            }
        }
        // reset accumulators for next tile
        #pragma unroll
        for (int i = 0; i < 2; i++)
            #pragma unroll
            for (int j = 0; j < 4; j++)
                #pragma unroll
                for (int q2 = 0; q2 < 4; q2++) acc[i][j][q2] = 0.0f;
    };

    load_chunk(0, 0);
    if (total > 1) load_chunk(1, 1);

    #pragma unroll 1
    for (int s = 0; s < total; s++) {
        if (s + 1 < total) { CP_WAIT(1); } else { CP_WAIT(0); }
        __syncthreads();

        const uint32_t aBh = sb + (s & 1) * GSTAGE;
        const uint32_t aBl = aBh + 16384;
        const uint32_t bBh = aBh + 32768;
        const uint32_t bBl = aBh + 40960;

        #pragma unroll
        for (int ks = 0; ks < 4; ks++) {
            uint32_t ah[2][4], al[2][4];
            const int cA = ks * 2 + aColSl;
            #pragma unroll
            for (int i = 0; i < 2; i++) {
                int row = warpM + i * 16 + aRow;
                uint32_t off = SWZC(row, cA);
                ldmx4(ah[i], aBh + off);
                ldmx4(al[i], aBl + off);
            }
            // B via ldmatrix.x4: groups (j,ksl0),(j,ksl1),(j+1,ksl0),(j+1,ksl1)
            uint32_t bh[4][2], bl[4][2];
            #pragma unroll
            for (int jp = 0; jp < 2; jp++) {
                int row = warpN + jp * 16 + (bg >> 1) * 8 + bgRow;
                uint32_t off = SWZC(row, ks * 2 + (bg & 1));
                ldmx4p(bh[jp*2][0], bh[jp*2][1], bh[jp*2+1][0], bh[jp*2+1][1],
                       bBh + off);
                ldmx4p(bl[jp*2][0], bl[jp*2][1], bl[jp*2+1][0], bl[jp*2+1][1],
                       bBl + off);
            }
            #pragma unroll
            for (int i = 0; i < 2; i++)
                #pragma unroll
                for (int j = 0; j < 4; j++) {
                    mma16816(acc[i][j], ah[i], bh[j]);
                    mma16816(acc[i][j], ah[i], bl[j]);
                    mma16816(acc[i][j], al[i], bh[j]);
                }
        }

        __syncthreads();                     // all reads of stage (s&1) done
        if (s + 2 < total) load_chunk(s + 2, s & 1);
        if ((s & 7) == 7) epilogue(s >> 3);  // after next loads are in flight
    }
}

// ---------------------------------------------------------------------------
// h1 = relu(mean3(P[faces]) + b1) -> bf16 hi/lo.
// ---------------------------------------------------------------------------
__global__ void gather_mean_split_kernel(const int* __restrict__ faces,
                                         const float* __restrict__ b1) {
    int idx = blockIdx.x * blockDim.x + threadIdx.x;
    int f  = idx >> 7;
    int c4 = (idx & 127) << 2;
    if (f >= N_FACES) return;
    int i0 = __ldg(&faces[f * 3 + 0]);
    int i1 = __ldg(&faces[f * 3 + 1]);
    int i2 = __ldg(&faces[f * 3 + 2]);
    float4 a = *(const float4*)&g_P[(size_t)i0 * DIMD + c4];
    float4 b = *(const float4*)&g_P[(size_t)i1 * DIMD + c4];
    float4 c = *(const float4*)&g_P[(size_t)i2 * DIMD + c4];
    float4 bb = *(const float4*)&b1[c4];
    const float k = 1.0f / 3.0f;
    float v0 = fmaxf((a.x + b.x + c.x) * k + bb.x, 0.0f);
    float v1 = fmaxf((a.y + b.y + c.y) * k + bb.y, 0.0f);
    float v2 = fmaxf((a.z + b.z + c.z) * k + bb.z, 0.0f);
    float v3 = fmaxf((a.w + b.w + c.w) * k + bb.w, 0.0f);
    __nv_bfloat16 h0 = __float2bfloat16(v0);
    __nv_bfloat16 h1 = __float2bfloat16(v1);
    __nv_bfloat16 h2 = __float2bfloat16(v2);
    __nv_bfloat16 h3 = __float2bfloat16(v3);
    __nv_bfloat16 l0 = __float2bfloat16(v0 - __bfloat162float(h0));
    __nv_bfloat16 l1 = __float2bfloat16(v1 - __bfloat162float(h1));
    __nv_bfloat16 l2 = __float2bfloat16(v2 - __bfloat162float(h2));
    __nv_bfloat16 l3 = __float2bfloat16(v3 - __bfloat162float(h3));
    size_t o = (size_t)f * DIMD + c4;
    *(uint2*)&g_A1H[o] = make_uint2(packbf2(h0, h1), packbf2(h2, h3));
    *(uint2*)&g_A1L[o] = make_uint2(packbf2(l0, l1), packbf2(l2, l3));
}

// ---------------------------------------------------------------------------
// out12 = (h3_hi + h3_lo) @ W4 + b4
// ---------------------------------------------------------------------------
__global__ __launch_bounds__(128)
void out12_kernel(const float* __restrict__ W4, const float* __restrict__ b4) {
    __shared__ float ws[256 * 12];
    for (int i = threadIdx.x; i < 256 * 12; i += blockDim.x) ws[i] = W4[i];
    __syncthreads();
    int r = blockIdx.x * blockDim.x + threadIdx.x;
    if (r >= N_FACES) return;
    const __nv_bfloat16* xh = g_H3H + (size_t)r * 256;
    const __nv_bfloat16* xl = g_H3L + (size_t)r * 256;
    float acc[12];
    #pragma unroll
    for (int n = 0; n < 12; n++) acc[n] = b4[n];
    for (int k = 0; k < 256; k += 8) {
        uint4 uh = *(const uint4*)&xh[k];
        uint4 ul = *(const uint4*)&xl[k];
        const uint32_t hu[4] = {uh.x, uh.y, uh.z, uh.w};
        const uint32_t lu[4] = {ul.x, ul.y, ul.z, ul.w};
        #pragma unroll
        for (int t = 0; t < 4; t++) {
            __nv_bfloat162 hb = *(const __nv_bfloat162*)&hu[t];
            __nv_bfloat162 lb = *(const __nv_bfloat162*)&lu[t];
            float v0 = __bfloat162float(hb.x) + __bfloat162float(lb.x);
            float v1 = __bfloat162float(hb.y) + __bfloat162float(lb.y);
            int kk = k + t * 2;
            #pragma unroll
            for (int n = 0; n < 12; n++) {
                acc[n] = fmaf(v0, ws[kk * 12 + n], acc[n]);
                acc[n] = fmaf(v1, ws[(kk + 1) * 12 + n], acc[n]);
            }
        }
    }
    #pragma unroll
    for (int n = 0; n < 12; n++) g_out12[(size_t)r * 12 + n] = acc[n];
}

// ---------------------------------------------------------------------------
// 3x3 Jacobi + special procrustes + transform + segment atomics
// ---------------------------------------------------------------------------
__device__ __forceinline__ void jrot(float A[3][3], float V[3][3],
                                     int p, int q, int r) {
    float apq = A[p][q];
    if (fabsf(apq) < 1e-20f) return;
    float tau = (A[q][q] - A[p][p]) / (2.0f * apq);
    float t = copysignf(1.0f, tau) / (fabsf(tau) + sqrtf(1.0f + tau * tau));
    float c = rsqrtf(1.0f + t * t);
    float s = t * c;
    A[p][p] -= t * apq;
    A[q][q] += t * apq;
    A[p][q] = 0.0f; A[q][p] = 0.0f;
    float arp = A[r][p], arq = A[r][q];
    A[r][p] = c * arp - s * arq; A[p][r] = A[r][p];
    A[r][q] = s * arp + c * arq; A[q][r] = A[r][q];
    #pragma unroll
    for (int k = 0; k < 3; k++) {
        float vkp = V[k][p], vkq = V[k][q];
        V[k][p] = c * vkp - s * vkq;
        V[k][q] = s * vkp + c * vkq;
    }
}

__device__ __forceinline__ void cross3(const float a[3], const float b[3], float o[3]) {
    o[0] = a[1] * b[2] - a[2] * b[1];
    o[1] = a[2] * b[0] - a[0] * b[2];
    o[2] = a[0] * b[1] - a[1] * b[0];
}

__global__ __launch_bounds__(256)
void procrustes_kernel(const float* __restrict__ verts,
                       const int*   __restrict__ faces,
                       float* __restrict__ out) {
    int f = blockIdx.x * blockDim.x + threadIdx.x;
    if (f >= N_FACES) return;

    float o[12];
    #pragma unroll
    for (int i = 0; i < 12; i++) o[i] = g_out12[(size_t)f * 12 + i];

    float m[3][3];
    #pragma unroll
    for (int i = 0; i < 3; i++)
        #pragma unroll
        for (int j = 0; j < 3; j++) m[i][j] = o[3 * i + j];

    float fr = 0.0f;
    #pragma unroll
    for (int i = 0; i < 3; i++)
        #pragma unroll
        for (int j = 0; j < 3; j++) fr += m[i][j] * m[i][j];
    float inv = rsqrtf(fmaxf(fr, 1e-30f));
    #pragma unroll
    for (int i = 0; i < 3; i++)
        #pragma unroll
        for (int j = 0; j < 3; j++) m[i][j] *= inv;

    float A[3][3];
    #pragma unroll
    for (int i = 0; i < 3; i++)
        #pragma unroll
        for (int j = 0; j < 3; j++) {
            float s = 0.0f;
            #pragma unroll
            for (int k = 0; k < 3; k++) s += m[k][i] * m[k][j];
            A[i][j] = s;
        }
    float V[3][3] = {{1,0,0},{0,1,0},{0,0,1}};

    #pragma unroll
    for (int sweep = 0; sweep < 6; sweep++) {
        jrot(A, V, 0, 1, 2);
        jrot(A, V, 0, 2, 1);
        jrot(A, V, 1, 2, 0);
    }

    float w0 = A[0][0], w1 = A[1][1], w2 = A[2][2];
    int imax = (w0 >= w1) ? (w0 >= w2 ? 0 : 2) : (w1 >= w2 ? 1 : 2);
    int imin = (w0 <= w1) ? (w0 <= w2 ? 0 : 2) : (w1 <= w2 ? 1 : 2);
    if (imax == imin) imin = (imax + 1) % 3;
    int imid = 3 - imax - imin;

    float v1[3] = {V[0][imax], V[1][imax], V[2][imax]};
    float v2[3] = {V[0][imid], V[1][imid], V[2][imid]};

    float u1[3], u2[3];
    #pragma unroll
    for (int a = 0; a < 3; a++)
        u1[a] = m[a][0] * v1[0] + m[a][1] * v1[1] + m[a][2] * v1[2];
    float n1 = sqrtf(u1[0]*u1[0] + u1[1]*u1[1] + u1[2]*u1[2]);
    if (n1 > 1e-12f) {
        float in1 = 1.0f / n1;
        u1[0] *= in1; u1[1] *= in1; u1[2] *= in1;
    } else { u1[0] = 1.0f; u1[1] = 0.0f; u1[2] = 0.0f; }

    #pragma unroll
    for (int a = 0; a < 3; a++)
        u2[a] = m[a][0] * v2[0] + m[a][1] * v2[1] + m[a][2] * v2[2];
    float d = u2[0]*u1[0] + u2[1]*u1[1] + u2[2]*u1[2];
    u2[0] -= d * u1[0]; u2[1] -= d * u1[1]; u2[2] -= d * u1[2];
    float n2 = sqrtf(u2[0]*u2[0] + u2[1]*u2[1] + u2[2]*u2[2]);
    if (n2 > 1e-10f) {
        float in2 = 1.0f / n2;
        u2[0] *= in2; u2[1] *= in2; u2[2] *= in2;
    } else {
        float e[3] = {0.f, 0.f, 0.f};
        e[(fabsf(u1[0]) < 0.9f) ? 0 : 1] = 1.0f;
        cross3(u1, e, u2);
        float nn = rsqrtf(fmaxf(u2[0]*u2[0]+u2[1]*u2[1]+u2[2]*u2[2], 1e-30f));
        u2[0] *= nn; u2[1] *= nn; u2[2] *= nn;
    }

    float u3[3], v3[3];
    cross3(u1, u2, u3);
    cross3(v1, v2, v3);

    float R[3][3];
    #pragma unroll
    for (int a = 0; a < 3; a++)
        #pragma unroll
        for (int b = 0; b < 3; b++)
            R[a][b] = u1[a]*v1[b] + u2[a]*v2[b] + u3[a]*v3[b];

    float* rot_out = out + (size_t)(N_VERTS * 3) + (size_t)N_FACES * 9 + (size_t)f * 9;
    #pragma unroll
    for (int a = 0; a < 3; a++)
        #pragma unroll
        for (int b = 0; b < 3; b++)
            rot_out[a * 3 + b] = R[a][b];

    float t0 = o[9], t1 = o[10], t2 = o[11];
    float* tp_out = out + (size_t)(N_VERTS * 3) + (size_t)f * 9;
    #pragma unroll
    for (int j = 0; j < 3; j++) {
        int vi = faces[f * 3 + j];
        float p0 = verts[(size_t)vi * 3 + 0];
        float p1 = verts[(size_t)vi * 3 + 1];
        float p2 = verts[(size_t)vi * 3 + 2];
        float tpx = p0 * R[0][0] + p1 * R[1][0] + p2 * R[2][0] + t0;
        float tpy = p0 * R[0][1] + p1 * R[1][1] + p2 * R[2][1] + t1;
        float tpz = p0 * R[0][2] + p1 * R[1][2] + p2 * R[2][2] + t2;
        tp_out[j * 3 + 0] = tpx;
        tp_out[j * 3 + 1] = tpy;
        tp_out[j * 3 + 2] = tpz;
        atomicAdd(&g_summed[(size_t)vi * 3 + 0], tpx);
        atomicAdd(&g_summed[(size_t)vi * 3 + 1], tpy);
        atomicAdd(&g_summed[(size_t)vi * 3 + 2], tpz);
        atomicAdd(&g_counts[vi], 1.0f);
    }
}

__global__ void finalize_kernel(float* __restrict__ out) {
    int v = blockIdx.x * blockDim.x + threadIdx.x;
    if (v >= N_VERTS) return;
    float c = fmaxf(g_counts[v], 1.0f);
    float ic = 1.0f / c;
    out[(size_t)v * 3 + 0] = g_summed[(size_t)v * 3 + 0] * ic;
    out[(size_t)v * 3 + 1] = g_summed[(size_t)v * 3 + 1] * ic;
    out[(size_t)v * 3 + 2] = g_summed[(size_t)v * 3 + 2] * ic;
}

// ---------------------------------------------------------------------------
extern "C" void kernel_launch(void* const* d_in, const int* in_sizes, int n_in,
                              void* d_out, int out_size) {
    const float* verts    = (const float*)d_in[0];
    const float* features = (const float*)d_in[1];
    const int*   faces    = (const int*)  d_in[2];
    const float* W1 = (const float*)d_in[3];
    const float* b1 = (const float*)d_in[4];
    const float* W2 = (const float*)d_in[5];
    const float* b2 = (const float*)d_in[6];
    const float* W3 = (const float*)d_in[7];
    const float* b3 = (const float*)d_in[8];
    const float* W4 = (const float*)d_in[9];
    const float* b4 = (const float*)d_in[10];
    float* out = (float*)d_out;

    (void)in_sizes; (void)n_in; (void)out_size;

    cudaFuncSetAttribute(gemm_mma_persist,
                         cudaFuncAttributeMaxDynamicSharedMemorySize, GSMEM);

    zero_kernel<<<(N_VERTS * 3 + 255) / 256, 256>>>();

    convert_w<<<(512 * 512 + 255) / 256, 256>>>(W1, 8, 9, 512);
    convert_w<<<(512 * 512 + 255) / 256, 256>>>(W2, 10, 11, 512);
    convert_w<<<(256 * 512 + 255) / 256, 256>>>(W3, 12, 13, 256);

    split_feat_kernel<<<(N_VERTS * 128 + 255) / 256, 256>>>(features);

    // P = features @ W1t^T  (M = 100096, fp32 out, no bias)
    gemm_mma_persist<<<GRID_P, 256, GSMEM>>>(
        0, 1, 8, 9, b1, 0, 0, 0, 512, 8, (MPAD1 / 128) * 8);

    // h1 = relu(mean3(P[faces]) + b1) -> bf16 hi/lo
    gather_mean_split_kernel<<<(N_FACES * 128 + 255) / 256, 256>>>(faces, b1);

    // h2 = relu(h1 @ W2t^T + b2) -> A2
    gemm_mma_persist<<<GRID_P, 256, GSMEM>>>(
        2, 3, 10, 11, b2, 1, 4, 5, 512, 8, (MPAD / 128) * 8);

    // h3 = relu(h2 @ W3t^T + b3) -> H3
    gemm_mma_persist<<<GRID_P, 256, GSMEM>>>(
        4, 5, 12, 13, b3, 1, 6, 7, 256, 4, (MPAD / 128) * 4);

    out12_kernel<<<(N_FACES + 127) / 128, 128>>>(W4, b4);

    procrustes_kernel<<<(N_FACES + 255) / 256, 256>>>(verts, faces, out);

    finalize_kernel<<<(N_VERTS + 255) / 256, 256>>>(out);
}